// round 8
// baseline (speedup 1.0000x reference)
#include <cuda_runtime.h>

#define BATCH 8192
#define DIN   768
#define DSAE  12288
#define KTOP  64
#define CANDMAX 128

// scratch (__device__ globals are the sanctioned alloc-free scratch mechanism)
__device__ float g_cvals[BATCH * KTOP];
__device__ int   g_cidx [BATCH * KTOP];
__device__ int   g_G    [BATCH];              // definite-in count
__device__ int   g_C    [BATCH];              // candidate count (clamped)
__device__ int   g_need [BATCH];              // 64 - G
__device__ int   g_cand [BATCH * CANDMAX];    // candidate indices

// ---------------------------------------------------------------------------
// Kernel 1: encoder GEMM (fp32 FFMA, 128x128x16, 8x8 micro-tile)
// pre[m][n] = relu( sum_k (x[m][k]-b_dec[k]) * W_enc[k][n] + b_enc[n] )
// ---------------------------------------------------------------------------
__global__ __launch_bounds__(256, 2)
void enc_gemm(const float* __restrict__ x,
              const float* __restrict__ We,
              const float* __restrict__ be,
              const float* __restrict__ bd,
              float* __restrict__ pre)
{
    __shared__ float As[16][128];
    __shared__ float Bs[16][128];

    const int tid   = threadIdx.x;
    const int mBase = blockIdx.y * 128;
    const int nBase = blockIdx.x * 128;
    const int tx = tid & 15;
    const int ty = tid >> 4;

    float acc[8][8];
#pragma unroll
    for (int i = 0; i < 8; i++)
#pragma unroll
        for (int j = 0; j < 8; j++)
            acc[i][j] = 0.f;

    for (int kt = 0; kt < DIN; kt += 16) {
#pragma unroll
        for (int p = 0; p < 2; p++) {
            int idx = tid + p * 256;
            int r   = idx >> 2;
            int c4  = (idx & 3) * 4;
            float4 av = *(const float4*)(x + (size_t)(mBase + r) * DIN + kt + c4);
            float4 bv = *(const float4*)(bd + kt + c4);
            As[c4 + 0][r] = av.x - bv.x;
            As[c4 + 1][r] = av.y - bv.y;
            As[c4 + 2][r] = av.z - bv.z;
            As[c4 + 3][r] = av.w - bv.w;
        }
#pragma unroll
        for (int p = 0; p < 2; p++) {
            int idx = tid + p * 256;
            int kr  = idx >> 5;
            int nc  = (idx & 31) * 4;
            *(float4*)&Bs[kr][nc] =
                *(const float4*)(We + (size_t)(kt + kr) * DSAE + nBase + nc);
        }
        __syncthreads();

#pragma unroll
        for (int kk = 0; kk < 16; kk++) {
            float a[8], b[8];
            *(float4*)&a[0] = *(float4*)&As[kk][ty * 8];
            *(float4*)&a[4] = *(float4*)&As[kk][ty * 8 + 4];
            *(float4*)&b[0] = *(float4*)&Bs[kk][tx * 8];
            *(float4*)&b[4] = *(float4*)&Bs[kk][tx * 8 + 4];
#pragma unroll
            for (int i = 0; i < 8; i++)
#pragma unroll
                for (int j = 0; j < 8; j++)
                    acc[i][j] = fmaf(a[i], b[j], acc[i][j]);
        }
        __syncthreads();
    }

#pragma unroll
    for (int i = 0; i < 8; i++) {
        size_t m = (size_t)(mBase + ty * 8 + i);
#pragma unroll
        for (int j4 = 0; j4 < 8; j4 += 4) {
            int n = nBase + tx * 8 + j4;
            float4 bev = *(const float4*)(be + n);
            float4 o;
            o.x = fmaxf(acc[i][j4 + 0] + bev.x, 0.f);
            o.y = fmaxf(acc[i][j4 + 1] + bev.y, 0.f);
            o.z = fmaxf(acc[i][j4 + 2] + bev.z, 0.f);
            o.w = fmaxf(acc[i][j4 + 3] + bev.w, 0.f);
            *(float4*)(pre + m * DSAE + n) = o;
        }
    }
}

// ---------------------------------------------------------------------------
// Kernel 2: per-row top-64 threshold via 4-pass byte radix select, then margin
// classification: definite-in (v > T+m), definite-out (v < T-m), boundary
// candidates (|v-T| <= m) deferred to the refine kernel's scheme ranking.
// ---------------------------------------------------------------------------
#define CH  48   // elements per thread (12288 / 256), contiguous chunk
#define CHP 49   // padded chunk stride in smem

__global__ __launch_bounds__(256)
void topk_kernel(float* __restrict__ sparse)
{
    extern __shared__ float row[];            // 256 * CHP floats
    __shared__ unsigned hist[256];
    __shared__ unsigned scanbuf[256];
    __shared__ unsigned sh_bin;
    __shared__ int      sh_need;

    const int r   = blockIdx.x;
    const int tid = threadIdx.x;
    float* src = sparse + (size_t)r * DSAE;

    for (int i = tid; i < DSAE; i += 256)
        row[(i / CH) * CHP + (i % CH)] = src[i];
    __syncthreads();

    const float* myrow = row + tid * CHP;

    // ---- radix select 64th-largest (fp32 bits; all values >= +0) ----
    unsigned sel = 0, selmask = 0;
    int kneed = KTOP;
    for (int shift = 24; shift >= 0; shift -= 8) {
        hist[tid] = 0;
        __syncthreads();
#pragma unroll 4
        for (int j = 0; j < CH; j++) {
            unsigned u = __float_as_uint(myrow[j]);
            if ((u & selmask) == sel)
                atomicAdd(&hist[(u >> shift) & 255u], 1u);
        }
        __syncthreads();
        if (tid == 0) {
            unsigned cum = 0;
            int b = 255;
            for (; b >= 0; b--) {
                cum += hist[b];
                if ((int)cum >= kneed) break;
            }
            if (b < 0) b = 0;
            sh_bin  = (unsigned)b;
            sh_need = kneed - (int)(cum - hist[b]);
        }
        __syncthreads();
        sel     |= sh_bin << shift;
        selmask |= 255u << shift;
        kneed    = sh_need;
        __syncthreads();
    }

    const float t = __uint_as_float(sel);

    // ---- margin classification (retry with m=0 if too many candidates) ----
    float m = t * 1e-3f;
    float hi = t + m, lo = t - m;
    unsigned total = 0;

    for (int attempt = 0; attempt < 2; attempt++) {
        int cHi = 0, cCd = 0;
#pragma unroll 4
        for (int j = 0; j < CH; j++) {
            float v = myrow[j];
            cHi += (v > hi);
            cCd += (v >= lo) & (v <= hi);
        }
        unsigned mine = ((unsigned)cHi << 16) | (unsigned)cCd;
        scanbuf[tid] = mine;
        __syncthreads();
        for (int off = 1; off < 256; off <<= 1) {
            unsigned v = (tid >= off) ? scanbuf[tid - off] : 0u;
            __syncthreads();
            scanbuf[tid] += v;
            __syncthreads();
        }
        total = scanbuf[255];
        if ((total & 0xffffu) <= CANDMAX) break;
        hi = t; lo = t;   // shrink to exact ties only
        __syncthreads();
    }

    const int G = (int)(total >> 16);

    unsigned mine_now;
    {
        int cHi = 0, cCd = 0;
#pragma unroll 4
        for (int j = 0; j < CH; j++) {
            float v = myrow[j];
            cHi += (v > hi);
            cCd += (v >= lo) & (v <= hi);
        }
        mine_now = ((unsigned)cHi << 16) | (unsigned)cCd;
    }
    unsigned excl = scanbuf[tid] - mine_now;
    int hiBase = (int)(excl >> 16);
    int cdBase = (int)(excl & 0xffffu);

    // ---- write pass ----
    int localHi = 0, localCd = 0;
    for (int j = 0; j < CH; j++) {
        int i = tid * CH + j;
        float v = myrow[j];
        if (v > hi) {
            int slot = hiBase + localHi;
            g_cvals[r * KTOP + slot] = v;
            g_cidx [r * KTOP + slot] = i;
            localHi++;
            // src[i] already holds v
        } else if (v >= lo) {
            int cpos = cdBase + localCd;
            if (cpos < CANDMAX) g_cand[r * CANDMAX + cpos] = i;
            localCd++;
            // leave src[i]; refine kernel resolves
        } else {
            src[i] = 0.f;
        }
    }

    if (tid == 0) {
        int C = (int)(total & 0xffffu);
        if (C > CANDMAX) C = CANDMAX;
        g_G[r]    = G;
        g_C[r]    = C;
        g_need[r] = KTOP - G;
    }
}

// ---------------------------------------------------------------------------
// Kernel 2b: candidate rescoring replicating XLA:CPU Eigen contraction on
// Grace: multithreaded blocking branch with sysconf-queried L1 = 64KB hits
// the kc cap: k_cache = min((l1-ksub)/kdiv, 320) = 320 for every (mr,nr).
// k-panels {320, 320, 128}. Within a panel: single ascending FMA chain per
// output element (gebp keeps one accumulator lane per C element; vfmaq ==
// fmaf). Panel sums added sequentially into the fp32 C buffer. +b_enc, relu
// (exact no-ops here: biases are zero). Rank desc, ascending-index ties
// (XLA TopK is stable).
// ---------------------------------------------------------------------------
__global__ __launch_bounds__(128)
void refine_kernel(const float* __restrict__ x,
                   const float* __restrict__ We,
                   const float* __restrict__ be,
                   const float* __restrict__ bd,
                   float* __restrict__ sparse)
{
    __shared__ float cval[CANDMAX];
    __shared__ int   cidx[CANDMAX];
    __shared__ float xs[DIN];

    const int r    = blockIdx.x;
    const int tid  = threadIdx.x;

    const int G    = g_G[r];
    const int C    = g_C[r];
    const int need = g_need[r];

    for (int k = tid; k < DIN; k += 128)
        xs[k] = x[(size_t)r * DIN + k] - bd[k];
    if (tid < C) cidx[tid] = g_cand[r * CANDMAX + tid];
    __syncthreads();

    if (tid < C) {
        const int col = cidx[tid];
        const int kcs[4] = {0, 320, 640, 768};   // Eigen MT kc cap = 320
        float master = 0.f;
#pragma unroll 1
        for (int c = 0; c < 3; c++) {
            float chunk = 0.f;
#pragma unroll 1
            for (int k = kcs[c]; k < kcs[c + 1]; k++)
                chunk = fmaf(xs[k], We[(size_t)k * DSAE + col], chunk);
            master = master + chunk;   // one fp32 add per k-panel
        }
        master = master + be[col];
        cval[tid] = fmaxf(master, 0.f);
    }
    __syncthreads();

    if (tid < C) {
        float v = cval[tid];
        int   i = cidx[tid];
        unsigned u = __float_as_uint(v);
        int rank = 0;
        for (int k = 0; k < C; k++) {
            unsigned uk = __float_as_uint(cval[k]);
            rank += (uk > u) || (uk == u && cidx[k] < i);
        }
        float* src = sparse + (size_t)r * DSAE;
        if (rank < need) {
            src[i] = v;
            int slot = G + rank;
            g_cvals[r * KTOP + slot] = v;
            g_cidx [r * KTOP + slot] = i;
        } else {
            src[i] = 0.f;
        }
    }
}

// ---------------------------------------------------------------------------
// Kernel 3: sparse decode. recon[r] = b_dec + sum_j v_j * W_dec[idx_j, :]
// ---------------------------------------------------------------------------
__global__ __launch_bounds__(256)
void decode_kernel(const float* __restrict__ Wd,
                   const float* __restrict__ bd,
                   float* __restrict__ recon)
{
    __shared__ float sv[KTOP];
    __shared__ int   si[KTOP];
    const int r   = blockIdx.x;
    const int tid = threadIdx.x;
    if (tid < KTOP) {
        sv[tid] = g_cvals[r * KTOP + tid];
        si[tid] = g_cidx [r * KTOP + tid];
    }
    __syncthreads();

    float a0 = bd[tid];
    float a1 = bd[tid + 256];
    float a2 = bd[tid + 512];
#pragma unroll 4
    for (int j = 0; j < KTOP; j++) {
        const float* w = Wd + (size_t)si[j] * DIN;
        float v = sv[j];
        a0 = fmaf(v, w[tid],       a0);
        a1 = fmaf(v, w[tid + 256], a1);
        a2 = fmaf(v, w[tid + 512], a2);
    }
    float* out = recon + (size_t)r * DIN;
    out[tid]       = a0;
    out[tid + 256] = a1;
    out[tid + 512] = a2;
}

// ---------------------------------------------------------------------------
extern "C" void kernel_launch(void* const* d_in, const int* in_sizes, int n_in,
                              void* d_out, int out_size)
{
    const float* x  = (const float*)d_in[0];  // [8192, 768]
    const float* We = (const float*)d_in[1];  // [768, 12288]
    const float* be = (const float*)d_in[2];  // [12288]
    const float* Wd = (const float*)d_in[3];  // [12288, 768]
    const float* bd = (const float*)d_in[4];  // [768]

    float* out    = (float*)d_out;
    float* recon  = out;                               // [8192, 768]
    float* sparse = out + (size_t)BATCH * DIN;         // [8192, 12288]

    cudaFuncSetAttribute(topk_kernel,
                         cudaFuncAttributeMaxDynamicSharedMemorySize,
                         256 * CHP * 4);

    dim3 gemm_grid(DSAE / 128, BATCH / 128);   // (96, 64)
    enc_gemm<<<gemm_grid, 256>>>(x, We, be, bd, sparse);
    topk_kernel<<<BATCH, 256, 256 * CHP * 4>>>(sparse);
    refine_kernel<<<BATCH, 128>>>(x, We, be, bd, sparse);
    decode_kernel<<<BATCH, 256>>>(Wd, bd, recon);
}

// round 10
// speedup vs baseline: 1.5331x; 1.5331x over previous
#include <cuda_runtime.h>
#include <cuda_bf16.h>
#include <cstdint>

#define BATCH 8192
#define DIN   768
#define DSAE  12288
#define KTOP  64
#define CANDMAX 128

// ---------------- scratch (__device__ globals = sanctioned scratch) --------
__device__ float g_cvals[BATCH * KTOP];
__device__ int   g_cidx [BATCH * KTOP];
__device__ int   g_G    [BATCH];
__device__ int   g_C    [BATCH];
__device__ int   g_need [BATCH];
__device__ int   g_cand [BATCH * CANDMAX];

// split-bf16 operands, K-major
__device__ __nv_bfloat16 g_Ah[BATCH * DIN];   // (x - b_dec) hi
__device__ __nv_bfloat16 g_Al[BATCH * DIN];   // (x - b_dec) lo
__device__ __nv_bfloat16 g_Bh[DSAE * DIN];    // W_enc^T hi  [n][k]
__device__ __nv_bfloat16 g_Bl[DSAE * DIN];    // W_enc^T lo  [n][k]

__device__ __forceinline__ uint32_t smem_u32(const void* p) {
    uint32_t a;
    asm("{ .reg .u64 t; cvta.to.shared.u64 t, %1; cvt.u32.u64 %0, t; }"
        : "=r"(a) : "l"(p));
    return a;
}
__device__ __forceinline__ void ldsm4(uint32_t* r, uint32_t addr) {
    asm volatile("ldmatrix.sync.aligned.m8n8.x4.shared.b16 {%0,%1,%2,%3}, [%4];"
                 : "=r"(r[0]), "=r"(r[1]), "=r"(r[2]), "=r"(r[3]) : "r"(addr));
}
__device__ __forceinline__ void mma16816(float* c, const uint32_t* a, const uint32_t* b) {
    asm volatile(
        "mma.sync.aligned.m16n8k16.row.col.f32.bf16.bf16.f32 "
        "{%0,%1,%2,%3}, {%4,%5,%6,%7}, {%8,%9}, {%0,%1,%2,%3};"
        : "+f"(c[0]), "+f"(c[1]), "+f"(c[2]), "+f"(c[3])
        : "r"(a[0]), "r"(a[1]), "r"(a[2]), "r"(a[3]), "r"(b[0]), "r"(b[1]));
}

// ---------------------------------------------------------------------------
// conv A: a = x - b_dec -> bf16 hi/lo
// ---------------------------------------------------------------------------
__global__ __launch_bounds__(256)
void convA(const float* __restrict__ x, const float* __restrict__ bd)
{
    int idx = blockIdx.x * 256 + threadIdx.x;
    if (idx >= BATCH * DIN) return;
    int k = idx % DIN;
    float a = x[idx] - bd[k];
    __nv_bfloat16 h = __float2bfloat16(a);
    __nv_bfloat16 l = __float2bfloat16(a - __bfloat162float(h));
    g_Ah[idx] = h;
    g_Al[idx] = l;
}

// ---------------------------------------------------------------------------
// conv B: W_enc [768,12288] -> transposed [12288][768] bf16 hi/lo
// ---------------------------------------------------------------------------
__global__ __launch_bounds__(256)
void convB(const float* __restrict__ We)
{
    __shared__ float tile[32][33];
    int tx = threadIdx.x & 31, ty = threadIdx.x >> 5;
    int nBase = blockIdx.x * 32;
    int kBase = blockIdx.y * 32;
#pragma unroll
    for (int r = 0; r < 4; r++)
        tile[ty + r * 8][tx] = We[(size_t)(kBase + ty + r * 8) * DSAE + nBase + tx];
    __syncthreads();
#pragma unroll
    for (int r = 0; r < 4; r++) {
        int n = nBase + ty + r * 8;
        int k = kBase + tx;
        float v = tile[tx][ty + r * 8];
        __nv_bfloat16 h = __float2bfloat16(v);
        __nv_bfloat16 l = __float2bfloat16(v - __bfloat162float(h));
        g_Bh[(size_t)n * DIN + k] = h;
        g_Bl[(size_t)n * DIN + k] = l;
    }
}

// ---------------------------------------------------------------------------
// Kernel 1: encoder GEMM via mma.sync bf16 split (ah*bh + ah*bl + al*bh).
// CTA 128x128, BK=32, 8 warps (2m x 4n), warp tile 64x32, m16n8k16.
// pre[m][n] = relu(sum + b_enc[n]) written to the sparse region.
// ---------------------------------------------------------------------------
#define PAD 40   // bf16 row stride in smem (80B: 8-row ldmatrix conflict-free)

__global__ __launch_bounds__(256, 1)
void enc_gemm_mma(const float* __restrict__ be, float* __restrict__ pre)
{
    __shared__ __align__(16) __nv_bfloat16 sAh[128 * PAD];
    __shared__ __align__(16) __nv_bfloat16 sAl[128 * PAD];
    __shared__ __align__(16) __nv_bfloat16 sBh[128 * PAD];
    __shared__ __align__(16) __nv_bfloat16 sBl[128 * PAD];

    const int tid  = threadIdx.x;
    const int lane = tid & 31;
    const int wid  = tid >> 5;
    const int warpM = (wid >> 2) * 64;
    const int warpN = (wid & 3) * 32;
    const int mBase = blockIdx.y * 128;
    const int nBase = blockIdx.x * 128;

    const uint32_t uAh = smem_u32(sAh), uAl = smem_u32(sAl);
    const uint32_t uBh = smem_u32(sBh), uBl = smem_u32(sBl);

    float acc[4][4][4];
#pragma unroll
    for (int i = 0; i < 4; i++)
#pragma unroll
        for (int j = 0; j < 4; j++)
#pragma unroll
            for (int v = 0; v < 4; v++) acc[i][j][v] = 0.f;

    // per-thread load slots: 512 x 16B per matrix, 2 per thread
    const int row0 = tid >> 2;          // 0..63
    const int q    = (tid & 3) * 8;     // bf16 col offset 0,8,16,24

    uint4 pAh[2], pAl[2], pBh[2], pBl[2];

    // prefetch chunk 0
    {
        size_t ga0 = (size_t)(mBase + row0) * DIN + q;
        size_t ga1 = (size_t)(mBase + row0 + 64) * DIN + q;
        size_t gb0 = (size_t)(nBase + row0) * DIN + q;
        size_t gb1 = (size_t)(nBase + row0 + 64) * DIN + q;
        pAh[0] = *(const uint4*)(g_Ah + ga0);  pAh[1] = *(const uint4*)(g_Ah + ga1);
        pAl[0] = *(const uint4*)(g_Al + ga0);  pAl[1] = *(const uint4*)(g_Al + ga1);
        pBh[0] = *(const uint4*)(g_Bh + gb0);  pBh[1] = *(const uint4*)(g_Bh + gb1);
        pBl[0] = *(const uint4*)(g_Bl + gb0);  pBl[1] = *(const uint4*)(g_Bl + gb1);
    }

    const int aRow = lane & 15;          // ldmatrix A row
    const int aCol = (lane >> 4) * 8;    // ldmatrix A col8
    const int bg   = lane >> 3;          // ldmatrix B matrix group
    const int bRowOff = ((bg >> 1) * 8) + (lane & 7);
    const int bColOff = (bg & 1) * 8;

    for (int c = 0; c < DIN / 32; c++) {         // 24 chunks
        // store prefetched chunk to smem
        {
            int o0 = row0 * PAD + q;
            int o1 = (row0 + 64) * PAD + q;
            *(uint4*)(sAh + o0) = pAh[0];  *(uint4*)(sAh + o1) = pAh[1];
            *(uint4*)(sAl + o0) = pAl[0];  *(uint4*)(sAl + o1) = pAl[1];
            *(uint4*)(sBh + o0) = pBh[0];  *(uint4*)(sBh + o1) = pBh[1];
            *(uint4*)(sBl + o0) = pBl[0];  *(uint4*)(sBl + o1) = pBl[1];
        }
        __syncthreads();

        // prefetch next chunk (overlaps with compute below)
        if (c + 1 < DIN / 32) {
            int kof = (c + 1) * 32 + q;
            size_t ga0 = (size_t)(mBase + row0) * DIN + kof;
            size_t ga1 = (size_t)(mBase + row0 + 64) * DIN + kof;
            size_t gb0 = (size_t)(nBase + row0) * DIN + kof;
            size_t gb1 = (size_t)(nBase + row0 + 64) * DIN + kof;
            pAh[0] = *(const uint4*)(g_Ah + ga0);  pAh[1] = *(const uint4*)(g_Ah + ga1);
            pAl[0] = *(const uint4*)(g_Al + ga0);  pAl[1] = *(const uint4*)(g_Al + ga1);
            pBh[0] = *(const uint4*)(g_Bh + gb0);  pBh[1] = *(const uint4*)(g_Bh + gb1);
            pBl[0] = *(const uint4*)(g_Bl + gb0);  pBl[1] = *(const uint4*)(g_Bl + gb1);
        }

        // compute: 2 k16 steps
#pragma unroll
        for (int ks = 0; ks < 2; ks++) {
            uint32_t ah[4][4], al[4][4];
#pragma unroll
            for (int mt = 0; mt < 4; mt++) {
                uint32_t off = (uint32_t)((warpM + mt * 16 + aRow) * PAD +
                                          ks * 16 + aCol) * 2;
                ldsm4(ah[mt], uAh + off);
                ldsm4(al[mt], uAl + off);
            }
            uint32_t bh[4][2], bl[4][2];
#pragma unroll
            for (int i = 0; i < 2; i++) {
                uint32_t off = (uint32_t)((warpN + i * 16 + bRowOff) * PAD +
                                          bColOff + ks * 16) * 2;
                uint32_t t[4];
                ldsm4(t, uBh + off);
                bh[2 * i][0] = t[0]; bh[2 * i][1] = t[1];
                bh[2 * i + 1][0] = t[2]; bh[2 * i + 1][1] = t[3];
                ldsm4(t, uBl + off);
                bl[2 * i][0] = t[0]; bl[2 * i][1] = t[1];
                bl[2 * i + 1][0] = t[2]; bl[2 * i + 1][1] = t[3];
            }
#pragma unroll
            for (int mt = 0; mt < 4; mt++)
#pragma unroll
                for (int nt = 0; nt < 4; nt++) {
                    mma16816(acc[mt][nt], ah[mt], bh[nt]);
                    mma16816(acc[mt][nt], ah[mt], bl[nt]);
                    mma16816(acc[mt][nt], al[mt], bh[nt]);
                }
        }
        __syncthreads();
    }

    // epilogue: +b_enc, relu, store
#pragma unroll
    for (int mt = 0; mt < 4; mt++) {
#pragma unroll
        for (int nt = 0; nt < 4; nt++) {
            int m0 = mBase + warpM + mt * 16 + (lane >> 2);
            int n0 = nBase + warpN + nt * 8 + (lane & 3) * 2;
            float2 bev = *(const float2*)(be + n0);
            float2 o;
            o.x = fmaxf(acc[mt][nt][0] + bev.x, 0.f);
            o.y = fmaxf(acc[mt][nt][1] + bev.y, 0.f);
            *(float2*)(pre + (size_t)m0 * DSAE + n0) = o;
            o.x = fmaxf(acc[mt][nt][2] + bev.x, 0.f);
            o.y = fmaxf(acc[mt][nt][3] + bev.y, 0.f);
            *(float2*)(pre + (size_t)(m0 + 8) * DSAE + n0) = o;
        }
    }
}

// ---------------------------------------------------------------------------
// Kernel 2: per-row top-64 threshold via radix select + margin classification.
// (unchanged — known good)
// ---------------------------------------------------------------------------
#define CH  48
#define CHP 49

__global__ __launch_bounds__(256)
void topk_kernel(float* __restrict__ sparse)
{
    extern __shared__ float row[];
    __shared__ unsigned hist[256];
    __shared__ unsigned scanbuf[256];
    __shared__ unsigned sh_bin;
    __shared__ int      sh_need;

    const int r   = blockIdx.x;
    const int tid = threadIdx.x;
    float* src = sparse + (size_t)r * DSAE;

    for (int i = tid; i < DSAE; i += 256)
        row[(i / CH) * CHP + (i % CH)] = src[i];
    __syncthreads();

    const float* myrow = row + tid * CHP;

    unsigned sel = 0, selmask = 0;
    int kneed = KTOP;
    for (int shift = 24; shift >= 0; shift -= 8) {
        hist[tid] = 0;
        __syncthreads();
#pragma unroll 4
        for (int j = 0; j < CH; j++) {
            unsigned u = __float_as_uint(myrow[j]);
            if ((u & selmask) == sel)
                atomicAdd(&hist[(u >> shift) & 255u], 1u);
        }
        __syncthreads();
        if (tid == 0) {
            unsigned cum = 0;
            int b = 255;
            for (; b >= 0; b--) {
                cum += hist[b];
                if ((int)cum >= kneed) break;
            }
            if (b < 0) b = 0;
            sh_bin  = (unsigned)b;
            sh_need = kneed - (int)(cum - hist[b]);
        }
        __syncthreads();
        sel     |= sh_bin << shift;
        selmask |= 255u << shift;
        kneed    = sh_need;
        __syncthreads();
    }

    const float t = __uint_as_float(sel);

    float m = t * 1e-3f;
    float hi = t + m, lo = t - m;
    unsigned total = 0;

    for (int attempt = 0; attempt < 2; attempt++) {
        int cHi = 0, cCd = 0;
#pragma unroll 4
        for (int j = 0; j < CH; j++) {
            float v = myrow[j];
            cHi += (v > hi);
            cCd += (v >= lo) & (v <= hi);
        }
        unsigned mine = ((unsigned)cHi << 16) | (unsigned)cCd;
        scanbuf[tid] = mine;
        __syncthreads();
        for (int off = 1; off < 256; off <<= 1) {
            unsigned v = (tid >= off) ? scanbuf[tid - off] : 0u;
            __syncthreads();
            scanbuf[tid] += v;
            __syncthreads();
        }
        total = scanbuf[255];
        if ((total & 0xffffu) <= CANDMAX) break;
        hi = t; lo = t;
        __syncthreads();
    }

    const int G = (int)(total >> 16);

    unsigned mine_now;
    {
        int cHi = 0, cCd = 0;
#pragma unroll 4
        for (int j = 0; j < CH; j++) {
            float v = myrow[j];
            cHi += (v > hi);
            cCd += (v >= lo) & (v <= hi);
        }
        mine_now = ((unsigned)cHi << 16) | (unsigned)cCd;
    }
    unsigned excl = scanbuf[tid] - mine_now;
    int hiBase = (int)(excl >> 16);
    int cdBase = (int)(excl & 0xffffu);

    int localHi = 0, localCd = 0;
    for (int j = 0; j < CH; j++) {
        int i = tid * CH + j;
        float v = myrow[j];
        if (v > hi) {
            int slot = hiBase + localHi;
            g_cvals[r * KTOP + slot] = v;
            g_cidx [r * KTOP + slot] = i;
            localHi++;
        } else if (v >= lo) {
            int cpos = cdBase + localCd;
            if (cpos < CANDMAX) g_cand[r * CANDMAX + cpos] = i;
            localCd++;
        } else {
            src[i] = 0.f;
        }
    }

    if (tid == 0) {
        int C = (int)(total & 0xffffu);
        if (C > CANDMAX) C = CANDMAX;
        g_G[r]    = G;
        g_C[r]    = C;
        g_need[r] = KTOP - G;
    }
}

// ---------------------------------------------------------------------------
// Kernel 2b: Eigen-exact candidate rescoring, k-panels {320,320,128}.
// (unchanged — correctness anchor; do not modify)
// ---------------------------------------------------------------------------
__global__ __launch_bounds__(128)
void refine_kernel(const float* __restrict__ x,
                   const float* __restrict__ We,
                   const float* __restrict__ be,
                   const float* __restrict__ bd,
                   float* __restrict__ sparse)
{
    __shared__ float cval[CANDMAX];
    __shared__ int   cidx[CANDMAX];
    __shared__ float xs[DIN];

    const int r    = blockIdx.x;
    const int tid  = threadIdx.x;

    const int G    = g_G[r];
    const int C    = g_C[r];
    const int need = g_need[r];

    for (int k = tid; k < DIN; k += 128)
        xs[k] = x[(size_t)r * DIN + k] - bd[k];
    if (tid < C) cidx[tid] = g_cand[r * CANDMAX + tid];
    __syncthreads();

    if (tid < C) {
        const int col = cidx[tid];
        const int kcs[4] = {0, 320, 640, 768};
        float master = 0.f;
#pragma unroll 1
        for (int c = 0; c < 3; c++) {
            float chunk = 0.f;
#pragma unroll 1
            for (int k = kcs[c]; k < kcs[c + 1]; k++)
                chunk = fmaf(xs[k], We[(size_t)k * DSAE + col], chunk);
            master = master + chunk;
        }
        master = master + be[col];
        cval[tid] = fmaxf(master, 0.f);
    }
    __syncthreads();

    if (tid < C) {
        float v = cval[tid];
        int   i = cidx[tid];
        unsigned u = __float_as_uint(v);
        int rank = 0;
        for (int k = 0; k < C; k++) {
            unsigned uk = __float_as_uint(cval[k]);
            rank += (uk > u) || (uk == u && cidx[k] < i);
        }
        float* src = sparse + (size_t)r * DSAE;
        if (rank < need) {
            src[i] = v;
            int slot = G + rank;
            g_cvals[r * KTOP + slot] = v;
            g_cidx [r * KTOP + slot] = i;
        } else {
            src[i] = 0.f;
        }
    }
}

// ---------------------------------------------------------------------------
// Kernel 3: sparse decode (unchanged)
// ---------------------------------------------------------------------------
__global__ __launch_bounds__(256)
void decode_kernel(const float* __restrict__ Wd,
                   const float* __restrict__ bd,
                   float* __restrict__ recon)
{
    __shared__ float sv[KTOP];
    __shared__ int   si[KTOP];
    const int r   = blockIdx.x;
    const int tid = threadIdx.x;
    if (tid < KTOP) {
        sv[tid] = g_cvals[r * KTOP + tid];
        si[tid] = g_cidx [r * KTOP + tid];
    }
    __syncthreads();

    float a0 = bd[tid];
    float a1 = bd[tid + 256];
    float a2 = bd[tid + 512];
#pragma unroll 4
    for (int j = 0; j < KTOP; j++) {
        const float* w = Wd + (size_t)si[j] * DIN;
        float v = sv[j];
        a0 = fmaf(v, w[tid],       a0);
        a1 = fmaf(v, w[tid + 256], a1);
        a2 = fmaf(v, w[tid + 512], a2);
    }
    float* out = recon + (size_t)r * DIN;
    out[tid]       = a0;
    out[tid + 256] = a1;
    out[tid + 512] = a2;
}

// ---------------------------------------------------------------------------
extern "C" void kernel_launch(void* const* d_in, const int* in_sizes, int n_in,
                              void* d_out, int out_size)
{
    const float* x  = (const float*)d_in[0];
    const float* We = (const float*)d_in[1];
    const float* be = (const float*)d_in[2];
    const float* Wd = (const float*)d_in[3];
    const float* bd = (const float*)d_in[4];

    float* out    = (float*)d_out;
    float* recon  = out;
    float* sparse = out + (size_t)BATCH * DIN;

    cudaFuncSetAttribute(topk_kernel,
                         cudaFuncAttributeMaxDynamicSharedMemorySize, 256 * CHP * 4);

    convA<<<(BATCH * DIN + 255) / 256, 256>>>(x, bd);
    convB<<<dim3(DSAE / 32, DIN / 32), 256>>>(We);

    dim3 gemm_grid(DSAE / 128, BATCH / 128);   // (96, 64)
    enc_gemm_mma<<<gemm_grid, 256>>>(be, sparse);

    topk_kernel<<<BATCH, 256, 256 * CHP * 4>>>(sparse);
    refine_kernel<<<BATCH, 128>>>(x, We, be, bd, sparse);
    decode_kernel<<<BATCH, 256>>>(Wd, bd, recon);
}

// round 11
// speedup vs baseline: 2.7329x; 1.7826x over previous
#include <cuda_runtime.h>
#include <cuda_bf16.h>
#include <cstdint>

#define BATCH 8192
#define DIN   768
#define DSAE  12288
#define KTOP  64
#define CANDMAX 128

// ---------------- scratch (__device__ globals = sanctioned scratch) --------
__device__ float g_cvals[BATCH * KTOP];
__device__ int   g_cidx [BATCH * KTOP];
__device__ int   g_G    [BATCH];
__device__ int   g_C    [BATCH];
__device__ int   g_need [BATCH];
__device__ int   g_cand [BATCH * CANDMAX];

// split-bf16 operands, K-major
__device__ __nv_bfloat16 g_Ah[BATCH * DIN];
__device__ __nv_bfloat16 g_Al[BATCH * DIN];
__device__ __nv_bfloat16 g_Bh[DSAE * DIN];
__device__ __nv_bfloat16 g_Bl[DSAE * DIN];
// fp32 transposed encoder weights for refine (contiguous per-column reads)
__device__ float g_WeT[(size_t)DSAE * DIN];

__device__ __forceinline__ uint32_t smem_u32(const void* p) {
    uint32_t a;
    asm("{ .reg .u64 t; cvta.to.shared.u64 t, %1; cvt.u32.u64 %0, t; }"
        : "=r"(a) : "l"(p));
    return a;
}
__device__ __forceinline__ void ldsm4(uint32_t* r, uint32_t addr) {
    asm volatile("ldmatrix.sync.aligned.m8n8.x4.shared.b16 {%0,%1,%2,%3}, [%4];"
                 : "=r"(r[0]), "=r"(r[1]), "=r"(r[2]), "=r"(r[3]) : "r"(addr));
}
__device__ __forceinline__ void mma16816(float* c, const uint32_t* a, const uint32_t* b) {
    asm volatile(
        "mma.sync.aligned.m16n8k16.row.col.f32.bf16.bf16.f32 "
        "{%0,%1,%2,%3}, {%4,%5,%6,%7}, {%8,%9}, {%0,%1,%2,%3};"
        : "+f"(c[0]), "+f"(c[1]), "+f"(c[2]), "+f"(c[3])
        : "r"(a[0]), "r"(a[1]), "r"(a[2]), "r"(a[3]), "r"(b[0]), "r"(b[1]));
}
__device__ __forceinline__ void cp16(uint32_t saddr, const void* g) {
    asm volatile("cp.async.cg.shared.global [%0], [%1], 16;" :: "r"(saddr), "l"(g));
}

// ---------------------------------------------------------------------------
// conv A: a = x - b_dec -> bf16 hi/lo
// ---------------------------------------------------------------------------
__global__ __launch_bounds__(256)
void convA(const float* __restrict__ x, const float* __restrict__ bd)
{
    int idx = blockIdx.x * 256 + threadIdx.x;
    if (idx >= BATCH * DIN) return;
    int k = idx % DIN;
    float a = x[idx] - bd[k];
    __nv_bfloat16 h = __float2bfloat16(a);
    __nv_bfloat16 l = __float2bfloat16(a - __bfloat162float(h));
    g_Ah[idx] = h;
    g_Al[idx] = l;
}

// ---------------------------------------------------------------------------
// conv B: W_enc [768,12288] -> transposed [12288][768]: bf16 hi/lo + fp32
// ---------------------------------------------------------------------------
__global__ __launch_bounds__(256)
void convB(const float* __restrict__ We)
{
    __shared__ float tile[32][33];
    int tx = threadIdx.x & 31, ty = threadIdx.x >> 5;
    int nBase = blockIdx.x * 32;
    int kBase = blockIdx.y * 32;
#pragma unroll
    for (int r = 0; r < 4; r++)
        tile[ty + r * 8][tx] = We[(size_t)(kBase + ty + r * 8) * DSAE + nBase + tx];
    __syncthreads();
#pragma unroll
    for (int r = 0; r < 4; r++) {
        int n = nBase + ty + r * 8;
        int k = kBase + tx;
        float v = tile[tx][ty + r * 8];
        __nv_bfloat16 h = __float2bfloat16(v);
        __nv_bfloat16 l = __float2bfloat16(v - __bfloat162float(h));
        g_Bh[(size_t)n * DIN + k] = h;
        g_Bl[(size_t)n * DIN + k] = l;
        g_WeT[(size_t)n * DIN + k] = v;
    }
}

// ---------------------------------------------------------------------------
// Kernel 1: encoder GEMM via mma.sync bf16 split (ah*bh + ah*bl + al*bh),
// cp.async double-buffered. CTA 128x128, BK=32, 8 warps, warp tile 64x32.
// ---------------------------------------------------------------------------
#define PAD 40                      // bf16 row stride (80B)
#define MATB (128 * PAD * 2)        // 10240 B per matrix buffer
#define STAGEB (4 * MATB)           // 40960 B per stage
#define GEMM_SMEM (2 * STAGEB)      // 81920 B

__global__ __launch_bounds__(256)
void enc_gemm_mma(const float* __restrict__ be, float* __restrict__ pre)
{
    extern __shared__ char dsm[];
    const uint32_t sb = smem_u32(dsm);

    const int tid  = threadIdx.x;
    const int lane = tid & 31;
    const int wid  = tid >> 5;
    const int warpM = (wid >> 2) * 64;
    const int warpN = (wid & 3) * 32;
    const int mBase = blockIdx.y * 128;
    const int nBase = blockIdx.x * 128;

    float acc[4][4][4];
#pragma unroll
    for (int i = 0; i < 4; i++)
#pragma unroll
        for (int j = 0; j < 4; j++)
#pragma unroll
            for (int v = 0; v < 4; v++) acc[i][j][v] = 0.f;

    // cp.async mapping: per matrix 512 x 16B ops, 2 per thread
    const int r0 = tid >> 1;              // op row pair base
    // op id = tid + p*256 -> row = id>>2, seg = id&3
#define ISSUE_CHUNK(c, stage)                                                   \
    {                                                                           \
        int kof = (c) * 32;                                                     \
        uint32_t st = sb + (stage) * STAGEB;                                    \
        _Pragma("unroll")                                                       \
        for (int p = 0; p < 2; p++) {                                           \
            int id  = tid + p * 256;                                            \
            int row = id >> 2, seg = id & 3;                                    \
            uint32_t so = (uint32_t)(row * PAD + seg * 8) * 2;                  \
            size_t ga = (size_t)(mBase + row) * DIN + kof + seg * 8;            \
            size_t gb = (size_t)(nBase + row) * DIN + kof + seg * 8;            \
            cp16(st + 0 * MATB + so, g_Ah + ga);                                \
            cp16(st + 1 * MATB + so, g_Al + ga);                                \
            cp16(st + 2 * MATB + so, g_Bh + gb);                                \
            cp16(st + 3 * MATB + so, g_Bl + gb);                                \
        }                                                                       \
    }

    const int aRow = lane & 15;
    const int aCol = (lane >> 4) * 8;
    const int bg   = lane >> 3;
    const int bRowOff = ((bg >> 1) * 8) + (lane & 7);
    const int bColOff = (bg & 1) * 8;

    ISSUE_CHUNK(0, 0);
    asm volatile("cp.async.commit_group;" ::: "memory");

    for (int c = 0; c < DIN / 32; c++) {          // 24 chunks
        if (c + 1 < DIN / 32) {
            ISSUE_CHUNK(c + 1, (c + 1) & 1);
            asm volatile("cp.async.commit_group;" ::: "memory");
            asm volatile("cp.async.wait_group 1;" ::: "memory");
        } else {
            asm volatile("cp.async.wait_group 0;" ::: "memory");
        }
        __syncthreads();

        uint32_t st = sb + (c & 1) * STAGEB;
        uint32_t uAh = st, uAl = st + MATB, uBh = st + 2 * MATB, uBl = st + 3 * MATB;

#pragma unroll
        for (int ks = 0; ks < 2; ks++) {
            uint32_t ah[4][4], al[4][4];
#pragma unroll
            for (int mt = 0; mt < 4; mt++) {
                uint32_t off = (uint32_t)((warpM + mt * 16 + aRow) * PAD +
                                          ks * 16 + aCol) * 2;
                ldsm4(ah[mt], uAh + off);
                ldsm4(al[mt], uAl + off);
            }
            uint32_t bh[4][2], bl[4][2];
#pragma unroll
            for (int i = 0; i < 2; i++) {
                uint32_t off = (uint32_t)((warpN + i * 16 + bRowOff) * PAD +
                                          bColOff + ks * 16) * 2;
                uint32_t t[4];
                ldsm4(t, uBh + off);
                bh[2 * i][0] = t[0]; bh[2 * i][1] = t[1];
                bh[2 * i + 1][0] = t[2]; bh[2 * i + 1][1] = t[3];
                ldsm4(t, uBl + off);
                bl[2 * i][0] = t[0]; bl[2 * i][1] = t[1];
                bl[2 * i + 1][0] = t[2]; bl[2 * i + 1][1] = t[3];
            }
#pragma unroll
            for (int mt = 0; mt < 4; mt++)
#pragma unroll
                for (int nt = 0; nt < 4; nt++) {
                    mma16816(acc[mt][nt], ah[mt], bh[nt]);
                    mma16816(acc[mt][nt], ah[mt], bl[nt]);
                    mma16816(acc[mt][nt], al[mt], bh[nt]);
                }
        }
        __syncthreads();
    }
    (void)r0;

    // epilogue: +b_enc, relu, store
#pragma unroll
    for (int mt = 0; mt < 4; mt++) {
#pragma unroll
        for (int nt = 0; nt < 4; nt++) {
            int m0 = mBase + warpM + mt * 16 + (lane >> 2);
            int n0 = nBase + warpN + nt * 8 + (lane & 3) * 2;
            float2 bev = *(const float2*)(be + n0);
            float2 o;
            o.x = fmaxf(acc[mt][nt][0] + bev.x, 0.f);
            o.y = fmaxf(acc[mt][nt][1] + bev.y, 0.f);
            *(float2*)(pre + (size_t)m0 * DSAE + n0) = o;
            o.x = fmaxf(acc[mt][nt][2] + bev.x, 0.f);
            o.y = fmaxf(acc[mt][nt][3] + bev.y, 0.f);
            *(float2*)(pre + (size_t)(m0 + 8) * DSAE + n0) = o;
        }
    }
}

// ---------------------------------------------------------------------------
// block exclusive scan over 256 threads (shfl + 8 warp partials)
// ---------------------------------------------------------------------------
__device__ __forceinline__ unsigned block_scan_excl(unsigned v, unsigned* wsum,
                                                    unsigned& total)
{
    const int lane = threadIdx.x & 31, w = threadIdx.x >> 5;
    unsigned incl = v;
#pragma unroll
    for (int o = 1; o < 32; o <<= 1) {
        unsigned n = __shfl_up_sync(0xffffffffu, incl, o);
        if (lane >= o) incl += n;
    }
    if (lane == 31) wsum[w] = incl;
    __syncthreads();
    if (w == 0) {
        unsigned s = (lane < 8) ? wsum[lane] : 0u;
#pragma unroll
        for (int o = 1; o < 8; o <<= 1) {
            unsigned n = __shfl_up_sync(0xffffffffu, s, o);
            if (lane >= o) s += n;
        }
        if (lane < 8) wsum[lane] = s;
    }
    __syncthreads();
    unsigned base = w ? wsum[w - 1] : 0u;
    total = wsum[7];
    return base + incl - v;
}

// ---------------------------------------------------------------------------
// Kernel 2: streaming per-row top-64 (no smem row; row stays L2-resident).
// Radix select threshold T, margin band -> candidates for refine.
// Selection semantics identical to the R8 passing kernel; only the compact
// slot ordering is thread-major (deterministic).
// ---------------------------------------------------------------------------
__global__ __launch_bounds__(256)
void topk_kernel(float* __restrict__ sparse)
{
    __shared__ unsigned hist[256];
    __shared__ unsigned wsum[8];
    __shared__ unsigned sh_bin, sh_need;

    const int r   = blockIdx.x;
    const int tid = threadIdx.x;
    float* src = sparse + (size_t)r * DSAE;
    const float4* s4 = (const float4*)src;

    // ---- radix select 64th-largest (fp32 bits; all values >= +0) ----
    unsigned sel = 0, selmask = 0;
    int kneed = KTOP;
    for (int shift = 24; shift >= 0; shift -= 8) {
        hist[tid] = 0;
        __syncthreads();
#pragma unroll 2
        for (int j = 0; j < 12; j++) {
            float4 f = s4[j * 256 + tid];
            unsigned u;
            u = __float_as_uint(f.x); if ((u & selmask) == sel) atomicAdd(&hist[(u >> shift) & 255u], 1u);
            u = __float_as_uint(f.y); if ((u & selmask) == sel) atomicAdd(&hist[(u >> shift) & 255u], 1u);
            u = __float_as_uint(f.z); if ((u & selmask) == sel) atomicAdd(&hist[(u >> shift) & 255u], 1u);
            u = __float_as_uint(f.w); if ((u & selmask) == sel) atomicAdd(&hist[(u >> shift) & 255u], 1u);
        }
        __syncthreads();
        unsigned v = hist[255 - tid];
        unsigned total, excl = block_scan_excl(v, wsum, total);
        if ((int)excl < kneed && (int)(excl + v) >= kneed) {
            sh_bin  = (unsigned)(255 - tid);
            sh_need = (unsigned)(kneed - (int)excl);
        }
        __syncthreads();
        sel     |= sh_bin << shift;
        selmask |= 255u << shift;
        kneed    = (int)sh_need;
        __syncthreads();
    }

    const float t = __uint_as_float(sel);

    // ---- margin classification (retry with m=0 if too many candidates) ----
    float m = t * 1e-3f;
    float hi = t + m, lo = t - m;
    unsigned hiBase = 0, cdBase = 0, G = 0, C = 0;

    for (int attempt = 0; attempt < 2; attempt++) {
        unsigned cHi = 0, cCd = 0;
#pragma unroll 2
        for (int j = 0; j < 12; j++) {
            float4 f = s4[j * 256 + tid];
            cHi += (f.x > hi) + (f.y > hi) + (f.z > hi) + (f.w > hi);
            cCd += ((f.x >= lo) & (f.x <= hi)) + ((f.y >= lo) & (f.y <= hi))
                 + ((f.z >= lo) & (f.z <= hi)) + ((f.w >= lo) & (f.w <= hi));
        }
        unsigned mine = (cHi << 16) | cCd;
        unsigned total, excl = block_scan_excl(mine, wsum, total);
        hiBase = excl >> 16;  cdBase = excl & 0xffffu;
        G = total >> 16;      C = total & 0xffffu;
        if (C <= CANDMAX) break;
        hi = t; lo = t;
        __syncthreads();
    }

    // ---- write pass ----
    int localHi = 0, localCd = 0;
#pragma unroll 2
    for (int j = 0; j < 12; j++) {
        int q = j * 256 + tid;
        float4 f = s4[q];
        float4 o;
        float* fe = &f.x;
        float* oe = &o.x;
#pragma unroll
        for (int e = 0; e < 4; e++) {
            float v = fe[e];
            int idx = q * 4 + e;
            if (v > hi) {
                int slot = (int)hiBase + localHi;
                g_cvals[r * KTOP + slot] = v;
                g_cidx [r * KTOP + slot] = idx;
                localHi++;
                oe[e] = v;
            } else if (v >= lo) {
                int cpos = (int)cdBase + localCd;
                if (cpos < CANDMAX) g_cand[r * CANDMAX + cpos] = idx;
                localCd++;
                oe[e] = v;          // refine resolves
            } else {
                oe[e] = 0.f;
            }
        }
        ((float4*)src)[q] = o;
    }

    if (tid == 0) {
        int Cc = (int)C;
        if (Cc > CANDMAX) Cc = CANDMAX;
        g_G[r]    = (int)G;
        g_C[r]    = Cc;
        g_need[r] = KTOP - (int)G;
    }
}

// ---------------------------------------------------------------------------
// Kernel 2b: Eigen-exact candidate rescoring, k-panels {320,320,128}.
// Arithmetic unchanged (correctness anchor); loads now from contiguous g_WeT.
// ---------------------------------------------------------------------------
__global__ __launch_bounds__(128)
void refine_kernel(const float* __restrict__ x,
                   const float* __restrict__ be,
                   const float* __restrict__ bd,
                   float* __restrict__ sparse)
{
    __shared__ float cval[CANDMAX];
    __shared__ int   cidx[CANDMAX];
    __shared__ float xs[DIN];

    const int r    = blockIdx.x;
    const int tid  = threadIdx.x;

    const int G    = g_G[r];
    const int C    = g_C[r];
    const int need = g_need[r];

    for (int k = tid; k < DIN; k += 128)
        xs[k] = x[(size_t)r * DIN + k] - bd[k];
    if (tid < C) cidx[tid] = g_cand[r * CANDMAX + tid];
    __syncthreads();

    if (tid < C) {
        const int col = cidx[tid];
        const float* w = g_WeT + (size_t)col * DIN;
        const int kcs[4] = {0, 320, 640, 768};
        float master = 0.f;
#pragma unroll 1
        for (int c = 0; c < 3; c++) {
            float chunk = 0.f;
#pragma unroll 4
            for (int k = kcs[c]; k < kcs[c + 1]; k++)
                chunk = fmaf(xs[k], w[k], chunk);
            master = master + chunk;
        }
        master = master + be[col];
        cval[tid] = fmaxf(master, 0.f);
    }
    __syncthreads();

    if (tid < C) {
        float v = cval[tid];
        int   i = cidx[tid];
        unsigned u = __float_as_uint(v);
        int rank = 0;
        for (int k = 0; k < C; k++) {
            unsigned uk = __float_as_uint(cval[k]);
            rank += (uk > u) || (uk == u && cidx[k] < i);
        }
        float* src = sparse + (size_t)r * DSAE;
        if (rank < need) {
            src[i] = v;
            int slot = G + rank;
            g_cvals[r * KTOP + slot] = v;
            g_cidx [r * KTOP + slot] = i;
        } else {
            src[i] = 0.f;
        }
    }
}

// ---------------------------------------------------------------------------
// Kernel 3: sparse decode (unchanged)
// ---------------------------------------------------------------------------
__global__ __launch_bounds__(256)
void decode_kernel(const float* __restrict__ Wd,
                   const float* __restrict__ bd,
                   float* __restrict__ recon)
{
    __shared__ float sv[KTOP];
    __shared__ int   si[KTOP];
    const int r   = blockIdx.x;
    const int tid = threadIdx.x;
    if (tid < KTOP) {
        sv[tid] = g_cvals[r * KTOP + tid];
        si[tid] = g_cidx [r * KTOP + tid];
    }
    __syncthreads();

    float a0 = bd[tid];
    float a1 = bd[tid + 256];
    float a2 = bd[tid + 512];
#pragma unroll 4
    for (int j = 0; j < KTOP; j++) {
        const float* w = Wd + (size_t)si[j] * DIN;
        float v = sv[j];
        a0 = fmaf(v, w[tid],       a0);
        a1 = fmaf(v, w[tid + 256], a1);
        a2 = fmaf(v, w[tid + 512], a2);
    }
    float* out = recon + (size_t)r * DIN;
    out[tid]       = a0;
    out[tid + 256] = a1;
    out[tid + 512] = a2;
}

// ---------------------------------------------------------------------------
extern "C" void kernel_launch(void* const* d_in, const int* in_sizes, int n_in,
                              void* d_out, int out_size)
{
    const float* x  = (const float*)d_in[0];
    const float* We = (const float*)d_in[1];
    const float* be = (const float*)d_in[2];
    const float* Wd = (const float*)d_in[3];
    const float* bd = (const float*)d_in[4];

    float* out    = (float*)d_out;
    float* recon  = out;
    float* sparse = out + (size_t)BATCH * DIN;

    cudaFuncSetAttribute(enc_gemm_mma,
                         cudaFuncAttributeMaxDynamicSharedMemorySize, GEMM_SMEM);

    convA<<<(BATCH * DIN + 255) / 256, 256>>>(x, bd);
    convB<<<dim3(DSAE / 32, DIN / 32), 256>>>(We);

    dim3 gemm_grid(DSAE / 128, BATCH / 128);   // (96, 64)
    enc_gemm_mma<<<gemm_grid, 256, GEMM_SMEM>>>(be, sparse);

    topk_kernel<<<BATCH, 256>>>(sparse);
    refine_kernel<<<BATCH, 128>>>(x, be, bd, sparse);
    decode_kernel<<<BATCH, 256>>>(Wd, bd, recon);
}

// round 12
// speedup vs baseline: 2.9802x; 1.0905x over previous
#include <cuda_runtime.h>
#include <cuda_fp16.h>
#include <cstdint>

#define BATCH 8192
#define DIN   768
#define DSAE  12288
#define KTOP  64
#define CANDMAX 128

// ---------------- scratch (__device__ globals = sanctioned scratch) --------
__device__ float g_cvals[BATCH * KTOP];
__device__ int   g_cidx [BATCH * KTOP];
__device__ int   g_G    [BATCH];
__device__ int   g_C    [BATCH];
__device__ int   g_need [BATCH];
__device__ int   g_cand [BATCH * CANDMAX];

// fp16 operands, K-major
__device__ __half g_A[BATCH * DIN];            // x - b_dec
__device__ __half g_B[DSAE * DIN];             // W_enc^T  [n][k]
// fp32 transposed encoder weights for refine (contiguous per-column reads)
__device__ float g_WeT[(size_t)DSAE * DIN];

__device__ __forceinline__ uint32_t smem_u32(const void* p) {
    uint32_t a;
    asm("{ .reg .u64 t; cvta.to.shared.u64 t, %1; cvt.u32.u64 %0, t; }"
        : "=r"(a) : "l"(p));
    return a;
}
__device__ __forceinline__ void ldsm4(uint32_t* r, uint32_t addr) {
    asm volatile("ldmatrix.sync.aligned.m8n8.x4.shared.b16 {%0,%1,%2,%3}, [%4];"
                 : "=r"(r[0]), "=r"(r[1]), "=r"(r[2]), "=r"(r[3]) : "r"(addr));
}
__device__ __forceinline__ void mma16816h(float* c, const uint32_t* a, const uint32_t* b) {
    asm volatile(
        "mma.sync.aligned.m16n8k16.row.col.f32.f16.f16.f32 "
        "{%0,%1,%2,%3}, {%4,%5,%6,%7}, {%8,%9}, {%0,%1,%2,%3};"
        : "+f"(c[0]), "+f"(c[1]), "+f"(c[2]), "+f"(c[3])
        : "r"(a[0]), "r"(a[1]), "r"(a[2]), "r"(a[3]), "r"(b[0]), "r"(b[1]));
}
__device__ __forceinline__ void cp16(uint32_t saddr, const void* g) {
    asm volatile("cp.async.cg.shared.global [%0], [%1], 16;" :: "r"(saddr), "l"(g));
}

// ---------------------------------------------------------------------------
// conv A: a = x - b_dec -> fp16
// ---------------------------------------------------------------------------
__global__ __launch_bounds__(256)
void convA(const float* __restrict__ x, const float* __restrict__ bd)
{
    int idx = blockIdx.x * 256 + threadIdx.x;
    if (idx >= BATCH * DIN) return;
    int k = idx % DIN;
    g_A[idx] = __float2half(x[idx] - bd[k]);
}

// ---------------------------------------------------------------------------
// conv B: W_enc [768,12288] -> transposed [12288][768]: fp16 + fp32
// ---------------------------------------------------------------------------
__global__ __launch_bounds__(256)
void convB(const float* __restrict__ We)
{
    __shared__ float tile[32][33];
    int tx = threadIdx.x & 31, ty = threadIdx.x >> 5;
    int nBase = blockIdx.x * 32;
    int kBase = blockIdx.y * 32;
#pragma unroll
    for (int r = 0; r < 4; r++)
        tile[ty + r * 8][tx] = We[(size_t)(kBase + ty + r * 8) * DSAE + nBase + tx];
    __syncthreads();
#pragma unroll
    for (int r = 0; r < 4; r++) {
        int n = nBase + ty + r * 8;
        int k = kBase + tx;
        float v = tile[tx][ty + r * 8];
        g_B  [(size_t)n * DIN + k] = __float2half(v);
        g_WeT[(size_t)n * DIN + k] = v;
    }
}

// ---------------------------------------------------------------------------
// Kernel 1: encoder GEMM, single fp16 mma.sync, cp.async double-buffered.
// CTA 128x128, BK=32, 8 warps (2m x 4n), warp tile 64x32, m16n8k16.
// ---------------------------------------------------------------------------
#define PAD 40                      // half row stride (80B)
#define MATB (128 * PAD * 2)        // 10240 B per matrix buffer
#define STAGEB (2 * MATB)           // 20480 B per stage (A + B)
#define GEMM_SMEM (2 * STAGEB)      // 40960 B

__global__ __launch_bounds__(256)
void enc_gemm_mma(const float* __restrict__ be, float* __restrict__ pre)
{
    extern __shared__ char dsm[];
    const uint32_t sb = smem_u32(dsm);

    const int tid  = threadIdx.x;
    const int lane = tid & 31;
    const int wid  = tid >> 5;
    const int warpM = (wid >> 2) * 64;
    const int warpN = (wid & 3) * 32;
    const int mBase = blockIdx.y * 128;
    const int nBase = blockIdx.x * 128;

    float acc[4][4][4];
#pragma unroll
    for (int i = 0; i < 4; i++)
#pragma unroll
        for (int j = 0; j < 4; j++)
#pragma unroll
            for (int v = 0; v < 4; v++) acc[i][j][v] = 0.f;

    // per stage: A = 512 x 16B ops, B = 512 x 16B ops; 2+2 per thread
#define ISSUE_CHUNK(c, stage)                                                   \
    {                                                                           \
        int kof = (c) * 32;                                                     \
        uint32_t st = sb + (stage) * STAGEB;                                    \
        _Pragma("unroll")                                                       \
        for (int p = 0; p < 2; p++) {                                           \
            int id  = tid + p * 256;                                            \
            int row = id >> 2, seg = id & 3;                                    \
            uint32_t so = (uint32_t)(row * PAD + seg * 8) * 2;                  \
            size_t ga = (size_t)(mBase + row) * DIN + kof + seg * 8;            \
            size_t gb = (size_t)(nBase + row) * DIN + kof + seg * 8;            \
            cp16(st + so, g_A + ga);                                            \
            cp16(st + MATB + so, g_B + gb);                                     \
        }                                                                       \
    }

    const int aRow = lane & 15;
    const int aCol = (lane >> 4) * 8;
    const int bg   = lane >> 3;
    const int bRowOff = ((bg >> 1) * 8) + (lane & 7);
    const int bColOff = (bg & 1) * 8;

    ISSUE_CHUNK(0, 0);
    asm volatile("cp.async.commit_group;" ::: "memory");

    for (int c = 0; c < DIN / 32; c++) {          // 24 chunks
        if (c + 1 < DIN / 32) {
            ISSUE_CHUNK(c + 1, (c + 1) & 1);
            asm volatile("cp.async.commit_group;" ::: "memory");
            asm volatile("cp.async.wait_group 1;" ::: "memory");
        } else {
            asm volatile("cp.async.wait_group 0;" ::: "memory");
        }
        __syncthreads();

        uint32_t st = sb + (c & 1) * STAGEB;
        uint32_t uA = st, uB = st + MATB;

#pragma unroll
        for (int ks = 0; ks < 2; ks++) {
            uint32_t a[4][4];
#pragma unroll
            for (int mt = 0; mt < 4; mt++) {
                uint32_t off = (uint32_t)((warpM + mt * 16 + aRow) * PAD +
                                          ks * 16 + aCol) * 2;
                ldsm4(a[mt], uA + off);
            }
            uint32_t b[4][2];
#pragma unroll
            for (int i = 0; i < 2; i++) {
                uint32_t off = (uint32_t)((warpN + i * 16 + bRowOff) * PAD +
                                          bColOff + ks * 16) * 2;
                uint32_t t[4];
                ldsm4(t, uB + off);
                b[2 * i][0] = t[0]; b[2 * i][1] = t[1];
                b[2 * i + 1][0] = t[2]; b[2 * i + 1][1] = t[3];
            }
#pragma unroll
            for (int mt = 0; mt < 4; mt++)
#pragma unroll
                for (int nt = 0; nt < 4; nt++)
                    mma16816h(acc[mt][nt], a[mt], b[nt]);
        }
        __syncthreads();
    }

    // epilogue: +b_enc, relu, store
#pragma unroll
    for (int mt = 0; mt < 4; mt++) {
#pragma unroll
        for (int nt = 0; nt < 4; nt++) {
            int m0 = mBase + warpM + mt * 16 + (lane >> 2);
            int n0 = nBase + warpN + nt * 8 + (lane & 3) * 2;
            float2 bev = *(const float2*)(be + n0);
            float2 o;
            o.x = fmaxf(acc[mt][nt][0] + bev.x, 0.f);
            o.y = fmaxf(acc[mt][nt][1] + bev.y, 0.f);
            *(float2*)(pre + (size_t)m0 * DSAE + n0) = o;
            o.x = fmaxf(acc[mt][nt][2] + bev.x, 0.f);
            o.y = fmaxf(acc[mt][nt][3] + bev.y, 0.f);
            *(float2*)(pre + (size_t)(m0 + 8) * DSAE + n0) = o;
        }
    }
}

// ---------------------------------------------------------------------------
// block exclusive scan over 256 threads (shfl + 8 warp partials)
// ---------------------------------------------------------------------------
__device__ __forceinline__ unsigned block_scan_excl(unsigned v, unsigned* wsum,
                                                    unsigned& total)
{
    const int lane = threadIdx.x & 31, w = threadIdx.x >> 5;
    unsigned incl = v;
#pragma unroll
    for (int o = 1; o < 32; o <<= 1) {
        unsigned n = __shfl_up_sync(0xffffffffu, incl, o);
        if (lane >= o) incl += n;
    }
    if (lane == 31) wsum[w] = incl;
    __syncthreads();
    if (w == 0) {
        unsigned s = (lane < 8) ? wsum[lane] : 0u;
#pragma unroll
        for (int o = 1; o < 8; o <<= 1) {
            unsigned n = __shfl_up_sync(0xffffffffu, s, o);
            if (lane >= o) s += n;
        }
        if (lane < 8) wsum[lane] = s;
    }
    __syncthreads();
    unsigned base = w ? wsum[w - 1] : 0u;
    total = wsum[7];
    return base + incl - v;
}

// ---------------------------------------------------------------------------
// Kernel 2: streaming per-row top-64. Margin widened to 4e-3*t to absorb
// single-fp16 GEMM noise (25 sigma); band resolved Eigen-exactly in refine.
// ---------------------------------------------------------------------------
__global__ __launch_bounds__(256)
void topk_kernel(float* __restrict__ sparse)
{
    __shared__ unsigned hist[256];
    __shared__ unsigned wsum[8];
    __shared__ unsigned sh_bin, sh_need;

    const int r   = blockIdx.x;
    const int tid = threadIdx.x;
    float* src = sparse + (size_t)r * DSAE;
    const float4* s4 = (const float4*)src;

    unsigned sel = 0, selmask = 0;
    int kneed = KTOP;
    for (int shift = 24; shift >= 0; shift -= 8) {
        hist[tid] = 0;
        __syncthreads();
#pragma unroll 2
        for (int j = 0; j < 12; j++) {
            float4 f = s4[j * 256 + tid];
            unsigned u;
            u = __float_as_uint(f.x); if ((u & selmask) == sel) atomicAdd(&hist[(u >> shift) & 255u], 1u);
            u = __float_as_uint(f.y); if ((u & selmask) == sel) atomicAdd(&hist[(u >> shift) & 255u], 1u);
            u = __float_as_uint(f.z); if ((u & selmask) == sel) atomicAdd(&hist[(u >> shift) & 255u], 1u);
            u = __float_as_uint(f.w); if ((u & selmask) == sel) atomicAdd(&hist[(u >> shift) & 255u], 1u);
        }
        __syncthreads();
        unsigned v = hist[255 - tid];
        unsigned total, excl = block_scan_excl(v, wsum, total);
        if ((int)excl < kneed && (int)(excl + v) >= kneed) {
            sh_bin  = (unsigned)(255 - tid);
            sh_need = (unsigned)(kneed - (int)excl);
        }
        __syncthreads();
        sel     |= sh_bin << shift;
        selmask |= 255u << shift;
        kneed    = (int)sh_need;
        __syncthreads();
    }

    const float t = __uint_as_float(sel);

    float m = t * 4e-3f;
    float hi = t + m, lo = t - m;
    unsigned hiBase = 0, cdBase = 0, G = 0, C = 0;

    for (int attempt = 0; attempt < 2; attempt++) {
        unsigned cHi = 0, cCd = 0;
#pragma unroll 2
        for (int j = 0; j < 12; j++) {
            float4 f = s4[j * 256 + tid];
            cHi += (f.x > hi) + (f.y > hi) + (f.z > hi) + (f.w > hi);
            cCd += ((f.x >= lo) & (f.x <= hi)) + ((f.y >= lo) & (f.y <= hi))
                 + ((f.z >= lo) & (f.z <= hi)) + ((f.w >= lo) & (f.w <= hi));
        }
        unsigned mine = (cHi << 16) | cCd;
        unsigned total, excl = block_scan_excl(mine, wsum, total);
        hiBase = excl >> 16;  cdBase = excl & 0xffffu;
        G = total >> 16;      C = total & 0xffffu;
        if (C <= CANDMAX) break;
        hi = t; lo = t;
        __syncthreads();
    }

    int localHi = 0, localCd = 0;
#pragma unroll 2
    for (int j = 0; j < 12; j++) {
        int q = j * 256 + tid;
        float4 f = s4[q];
        float4 o;
        float* fe = &f.x;
        float* oe = &o.x;
#pragma unroll
        for (int e = 0; e < 4; e++) {
            float v = fe[e];
            int idx = q * 4 + e;
            if (v > hi) {
                int slot = (int)hiBase + localHi;
                g_cvals[r * KTOP + slot] = v;
                g_cidx [r * KTOP + slot] = idx;
                localHi++;
                oe[e] = v;
            } else if (v >= lo) {
                int cpos = (int)cdBase + localCd;
                if (cpos < CANDMAX) g_cand[r * CANDMAX + cpos] = idx;
                localCd++;
                oe[e] = v;          // refine resolves
            } else {
                oe[e] = 0.f;
            }
        }
        ((float4*)src)[q] = o;
    }

    if (tid == 0) {
        int Cc = (int)C;
        if (Cc > CANDMAX) Cc = CANDMAX;
        g_G[r]    = (int)G;
        g_C[r]    = Cc;
        g_need[r] = KTOP - (int)G;
    }
}

// ---------------------------------------------------------------------------
// Kernel 2b: Eigen-exact candidate rescoring, k-panels {320,320,128}.
// (correctness anchor — arithmetic untouched)
// ---------------------------------------------------------------------------
__global__ __launch_bounds__(128)
void refine_kernel(const float* __restrict__ x,
                   const float* __restrict__ be,
                   const float* __restrict__ bd,
                   float* __restrict__ sparse)
{
    __shared__ float cval[CANDMAX];
    __shared__ int   cidx[CANDMAX];
    __shared__ float xs[DIN];

    const int r    = blockIdx.x;
    const int tid  = threadIdx.x;

    const int G    = g_G[r];
    const int C    = g_C[r];
    const int need = g_need[r];

    for (int k = tid; k < DIN; k += 128)
        xs[k] = x[(size_t)r * DIN + k] - bd[k];
    if (tid < C) cidx[tid] = g_cand[r * CANDMAX + tid];
    __syncthreads();

    if (tid < C) {
        const int col = cidx[tid];
        const float* w = g_WeT + (size_t)col * DIN;
        const int kcs[4] = {0, 320, 640, 768};
        float master = 0.f;
#pragma unroll 1
        for (int c = 0; c < 3; c++) {
            float chunk = 0.f;
#pragma unroll 4
            for (int k = kcs[c]; k < kcs[c + 1]; k++)
                chunk = fmaf(xs[k], w[k], chunk);
            master = master + chunk;
        }
        master = master + be[col];
        cval[tid] = fmaxf(master, 0.f);
    }
    __syncthreads();

    if (tid < C) {
        float v = cval[tid];
        int   i = cidx[tid];
        unsigned u = __float_as_uint(v);
        int rank = 0;
        for (int k = 0; k < C; k++) {
            unsigned uk = __float_as_uint(cval[k]);
            rank += (uk > u) || (uk == u && cidx[k] < i);
        }
        float* src = sparse + (size_t)r * DSAE;
        if (rank < need) {
            src[i] = v;
            int slot = G + rank;
            g_cvals[r * KTOP + slot] = v;
            g_cidx [r * KTOP + slot] = i;
        } else {
            src[i] = 0.f;
        }
    }
}

// ---------------------------------------------------------------------------
// Kernel 3: sparse decode (unchanged)
// ---------------------------------------------------------------------------
__global__ __launch_bounds__(256)
void decode_kernel(const float* __restrict__ Wd,
                   const float* __restrict__ bd,
                   float* __restrict__ recon)
{
    __shared__ float sv[KTOP];
    __shared__ int   si[KTOP];
    const int r   = blockIdx.x;
    const int tid = threadIdx.x;
    if (tid < KTOP) {
        sv[tid] = g_cvals[r * KTOP + tid];
        si[tid] = g_cidx [r * KTOP + tid];
    }
    __syncthreads();

    float a0 = bd[tid];
    float a1 = bd[tid + 256];
    float a2 = bd[tid + 512];
#pragma unroll 4
    for (int j = 0; j < KTOP; j++) {
        const float* w = Wd + (size_t)si[j] * DIN;
        float v = sv[j];
        a0 = fmaf(v, w[tid],       a0);
        a1 = fmaf(v, w[tid + 256], a1);
        a2 = fmaf(v, w[tid + 512], a2);
    }
    float* out = recon + (size_t)r * DIN;
    out[tid]       = a0;
    out[tid + 256] = a1;
    out[tid + 512] = a2;
}

// ---------------------------------------------------------------------------
extern "C" void kernel_launch(void* const* d_in, const int* in_sizes, int n_in,
                              void* d_out, int out_size)
{
    const float* x  = (const float*)d_in[0];
    const float* We = (const float*)d_in[1];
    const float* be = (const float*)d_in[2];
    const float* Wd = (const float*)d_in[3];
    const float* bd = (const float*)d_in[4];

    float* out    = (float*)d_out;
    float* recon  = out;
    float* sparse = out + (size_t)BATCH * DIN;

    cudaFuncSetAttribute(enc_gemm_mma,
                         cudaFuncAttributeMaxDynamicSharedMemorySize, GEMM_SMEM);

    convA<<<(BATCH * DIN + 255) / 256, 256>>>(x, bd);
    convB<<<dim3(DSAE / 32, DIN / 32), 256>>>(We);

    dim3 gemm_grid(DSAE / 128, BATCH / 128);   // (96, 64)
    enc_gemm_mma<<<gemm_grid, 256, GEMM_SMEM>>>(be, sparse);

    topk_kernel<<<BATCH, 256>>>(sparse);
    refine_kernel<<<BATCH, 128>>>(x, be, bd, sparse);
    decode_kernel<<<BATCH, 256>>>(Wd, bd, recon);
}

// round 13
// speedup vs baseline: 3.0496x; 1.0233x over previous
#include <cuda_runtime.h>
#include <cuda_fp16.h>
#include <cstdint>

#define BATCH 8192
#define DIN   768
#define DSAE  12288
#define KTOP  64
#define CANDMAX 128

// ---------------- scratch (__device__ globals = sanctioned scratch) --------
__device__ float g_cvals[BATCH * KTOP];
__device__ int   g_cidx [BATCH * KTOP];
__device__ int   g_G    [BATCH];
__device__ int   g_C    [BATCH];
__device__ int   g_need [BATCH];
__device__ int   g_cand [BATCH * CANDMAX];

// fp16 operands, K-major
__device__ __half g_A[BATCH * DIN];            // x - b_dec
__device__ __half g_B[DSAE * DIN];             // W_enc^T  [n][k]
// fp32 transposed encoder weights for refine
__device__ float g_WeT[(size_t)DSAE * DIN];

__device__ __forceinline__ uint32_t smem_u32(const void* p) {
    uint32_t a;
    asm("{ .reg .u64 t; cvta.to.shared.u64 t, %1; cvt.u32.u64 %0, t; }"
        : "=r"(a) : "l"(p));
    return a;
}
__device__ __forceinline__ void ldsm4(uint32_t* r, uint32_t addr) {
    asm volatile("ldmatrix.sync.aligned.m8n8.x4.shared.b16 {%0,%1,%2,%3}, [%4];"
                 : "=r"(r[0]), "=r"(r[1]), "=r"(r[2]), "=r"(r[3]) : "r"(addr));
}
__device__ __forceinline__ void mma16816h(float* c, const uint32_t* a, const uint32_t* b) {
    asm volatile(
        "mma.sync.aligned.m16n8k16.row.col.f32.f16.f16.f32 "
        "{%0,%1,%2,%3}, {%4,%5,%6,%7}, {%8,%9}, {%0,%1,%2,%3};"
        : "+f"(c[0]), "+f"(c[1]), "+f"(c[2]), "+f"(c[3])
        : "r"(a[0]), "r"(a[1]), "r"(a[2]), "r"(a[3]), "r"(b[0]), "r"(b[1]));
}
__device__ __forceinline__ void cp16(uint32_t saddr, const void* g) {
    asm volatile("cp.async.cg.shared.global [%0], [%1], 16;" :: "r"(saddr), "l"(g));
}

// ---------------------------------------------------------------------------
__global__ __launch_bounds__(256)
void convA(const float* __restrict__ x, const float* __restrict__ bd)
{
    int idx = blockIdx.x * 256 + threadIdx.x;
    if (idx >= BATCH * DIN) return;
    int k = idx % DIN;
    g_A[idx] = __float2half(x[idx] - bd[k]);
}

__global__ __launch_bounds__(256)
void convB(const float* __restrict__ We)
{
    __shared__ float tile[32][33];
    int tx = threadIdx.x & 31, ty = threadIdx.x >> 5;
    int nBase = blockIdx.x * 32;
    int kBase = blockIdx.y * 32;
#pragma unroll
    for (int r = 0; r < 4; r++)
        tile[ty + r * 8][tx] = We[(size_t)(kBase + ty + r * 8) * DSAE + nBase + tx];
    __syncthreads();
#pragma unroll
    for (int r = 0; r < 4; r++) {
        int n = nBase + ty + r * 8;
        int k = kBase + tx;
        float v = tile[tx][ty + r * 8];
        g_B  [(size_t)n * DIN + k] = __float2half(v);
        g_WeT[(size_t)n * DIN + k] = v;
    }
}

// ---------------------------------------------------------------------------
// Kernel 1: encoder GEMM, fp16 mma.sync, 3-stage cp.async pipeline.
// CTA 128x128, BK=32, 8 warps (2m x 4n), warp tile 64x32.
// ---------------------------------------------------------------------------
#define PAD 40                      // half row stride (80B)
#define MATB (128 * PAD * 2)        // 10240 B per matrix
#define STAGEB (2 * MATB)           // 20480 B per stage
#define NSTAGE 3
#define GEMM_SMEM (NSTAGE * STAGEB) // 61440 B

__global__ __launch_bounds__(256, 2)
void enc_gemm_mma(const float* __restrict__ be, float* __restrict__ pre)
{
    extern __shared__ char dsm[];
    const uint32_t sb = smem_u32(dsm);

    const int tid  = threadIdx.x;
    const int lane = tid & 31;
    const int wid  = tid >> 5;
    const int warpM = (wid >> 2) * 64;
    const int warpN = (wid & 3) * 32;
    const int mBase = blockIdx.y * 128;
    const int nBase = blockIdx.x * 128;

    float acc[4][4][4];
#pragma unroll
    for (int i = 0; i < 4; i++)
#pragma unroll
        for (int j = 0; j < 4; j++)
#pragma unroll
            for (int v = 0; v < 4; v++) acc[i][j][v] = 0.f;

#define ISSUE_CHUNK(c, stage)                                                   \
    {                                                                           \
        int kof = (c) * 32;                                                     \
        uint32_t st = sb + (stage) * STAGEB;                                    \
        _Pragma("unroll")                                                       \
        for (int p = 0; p < 2; p++) {                                           \
            int id  = tid + p * 256;                                            \
            int row = id >> 2, seg = id & 3;                                    \
            uint32_t so = (uint32_t)(row * PAD + seg * 8) * 2;                  \
            size_t ga = (size_t)(mBase + row) * DIN + kof + seg * 8;            \
            size_t gb = (size_t)(nBase + row) * DIN + kof + seg * 8;            \
            cp16(st + so, g_A + ga);                                            \
            cp16(st + MATB + so, g_B + gb);                                     \
        }                                                                       \
    }

    const int aRow = lane & 15;
    const int aCol = (lane >> 4) * 8;
    const int bg   = lane >> 3;
    const int bRowOff = ((bg >> 1) * 8) + (lane & 7);
    const int bColOff = (bg & 1) * 8;

    ISSUE_CHUNK(0, 0);
    asm volatile("cp.async.commit_group;" ::: "memory");
    ISSUE_CHUNK(1, 1);
    asm volatile("cp.async.commit_group;" ::: "memory");

    for (int c = 0; c < DIN / 32; c++) {          // 24 chunks
        asm volatile("cp.async.wait_group 1;" ::: "memory");
        __syncthreads();

        if (c + 2 < DIN / 32) {
            ISSUE_CHUNK(c + 2, (c + 2) % NSTAGE);
            asm volatile("cp.async.commit_group;" ::: "memory");
        }

        uint32_t st = sb + (c % NSTAGE) * STAGEB;
        uint32_t uA = st, uB = st + MATB;

#pragma unroll
        for (int ks = 0; ks < 2; ks++) {
            uint32_t a[4][4];
#pragma unroll
            for (int mt = 0; mt < 4; mt++) {
                uint32_t off = (uint32_t)((warpM + mt * 16 + aRow) * PAD +
                                          ks * 16 + aCol) * 2;
                ldsm4(a[mt], uA + off);
            }
            uint32_t b[4][2];
#pragma unroll
            for (int i = 0; i < 2; i++) {
                uint32_t off = (uint32_t)((warpN + i * 16 + bRowOff) * PAD +
                                          bColOff + ks * 16) * 2;
                uint32_t t[4];
                ldsm4(t, uB + off);
                b[2 * i][0] = t[0]; b[2 * i][1] = t[1];
                b[2 * i + 1][0] = t[2]; b[2 * i + 1][1] = t[3];
            }
#pragma unroll
            for (int mt = 0; mt < 4; mt++)
#pragma unroll
                for (int nt = 0; nt < 4; nt++)
                    mma16816h(acc[mt][nt], a[mt], b[nt]);
        }
        __syncthreads();
    }

    // epilogue: +b_enc, relu, store
#pragma unroll
    for (int mt = 0; mt < 4; mt++) {
#pragma unroll
        for (int nt = 0; nt < 4; nt++) {
            int m0 = mBase + warpM + mt * 16 + (lane >> 2);
            int n0 = nBase + warpN + nt * 8 + (lane & 3) * 2;
            float2 bev = *(const float2*)(be + n0);
            float2 o;
            o.x = fmaxf(acc[mt][nt][0] + bev.x, 0.f);
            o.y = fmaxf(acc[mt][nt][1] + bev.y, 0.f);
            *(float2*)(pre + (size_t)m0 * DSAE + n0) = o;
            o.x = fmaxf(acc[mt][nt][2] + bev.x, 0.f);
            o.y = fmaxf(acc[mt][nt][3] + bev.y, 0.f);
            *(float2*)(pre + (size_t)(m0 + 8) * DSAE + n0) = o;
        }
    }
}

// ---------------------------------------------------------------------------
// block exclusive scan over 256 threads (shfl + 8 warp partials)
// ---------------------------------------------------------------------------
__device__ __forceinline__ unsigned block_scan_excl(unsigned v, unsigned* wsum,
                                                    unsigned& total)
{
    const int lane = threadIdx.x & 31, w = threadIdx.x >> 5;
    unsigned incl = v;
#pragma unroll
    for (int o = 1; o < 32; o <<= 1) {
        unsigned n = __shfl_up_sync(0xffffffffu, incl, o);
        if (lane >= o) incl += n;
    }
    if (lane == 31) wsum[w] = incl;
    __syncthreads();
    if (w == 0) {
        unsigned s = (lane < 8) ? wsum[lane] : 0u;
#pragma unroll
        for (int o = 1; o < 8; o <<= 1) {
            unsigned n = __shfl_up_sync(0xffffffffu, s, o);
            if (lane >= o) s += n;
        }
        if (lane < 8) wsum[lane] = s;
    }
    __syncthreads();
    unsigned base = w ? wsum[w - 1] : 0u;
    total = wsum[7];
    return base + incl - v;
}

// ---------------------------------------------------------------------------
// Kernel 2: register-resident per-row top-64: the row is loaded ONCE into
// 48 registers/thread; all passes run from registers. One write back.
// ---------------------------------------------------------------------------
__global__ __launch_bounds__(256)
void topk_kernel(float* __restrict__ sparse)
{
    __shared__ unsigned hist[256];
    __shared__ unsigned wsum[8];
    __shared__ unsigned sh_bin, sh_need;

    const int r   = blockIdx.x;
    const int tid = threadIdx.x;
    float* src = sparse + (size_t)r * DSAE;
    const float4* s4 = (const float4*)src;

    float4 f[12];
#pragma unroll
    for (int j = 0; j < 12; j++) f[j] = s4[j * 256 + tid];

    // ---- radix select 64th-largest (fp32 bits; all values >= +0) ----
    unsigned sel = 0, selmask = 0;
    int kneed = KTOP;
    for (int shift = 24; shift >= 0; shift -= 8) {
        hist[tid] = 0;
        __syncthreads();
#pragma unroll
        for (int j = 0; j < 12; j++) {
            unsigned u;
            u = __float_as_uint(f[j].x); if ((u & selmask) == sel) atomicAdd(&hist[(u >> shift) & 255u], 1u);
            u = __float_as_uint(f[j].y); if ((u & selmask) == sel) atomicAdd(&hist[(u >> shift) & 255u], 1u);
            u = __float_as_uint(f[j].z); if ((u & selmask) == sel) atomicAdd(&hist[(u >> shift) & 255u], 1u);
            u = __float_as_uint(f[j].w); if ((u & selmask) == sel) atomicAdd(&hist[(u >> shift) & 255u], 1u);
        }
        __syncthreads();
        unsigned v = hist[255 - tid];
        unsigned total, excl = block_scan_excl(v, wsum, total);
        if ((int)excl < kneed && (int)(excl + v) >= kneed) {
            sh_bin  = (unsigned)(255 - tid);
            sh_need = (unsigned)(kneed - (int)excl);
        }
        __syncthreads();
        sel     |= sh_bin << shift;
        selmask |= 255u << shift;
        kneed    = (int)sh_need;
        __syncthreads();
    }

    const float t = __uint_as_float(sel);

    // ---- margin classification (4e-3: fp16 GEMM noise = ~25 sigma) ----
    float m = t * 4e-3f;
    float hi = t + m, lo = t - m;
    unsigned hiBase = 0, cdBase = 0, G = 0, C = 0;

    for (int attempt = 0; attempt < 2; attempt++) {
        unsigned cHi = 0, cCd = 0;
#pragma unroll
        for (int j = 0; j < 12; j++) {
            cHi += (f[j].x > hi) + (f[j].y > hi) + (f[j].z > hi) + (f[j].w > hi);
            cCd += ((f[j].x >= lo) & (f[j].x <= hi)) + ((f[j].y >= lo) & (f[j].y <= hi))
                 + ((f[j].z >= lo) & (f[j].z <= hi)) + ((f[j].w >= lo) & (f[j].w <= hi));
        }
        unsigned mine = (cHi << 16) | cCd;
        unsigned total, excl = block_scan_excl(mine, wsum, total);
        hiBase = excl >> 16;  cdBase = excl & 0xffffu;
        G = total >> 16;      C = total & 0xffffu;
        if (C <= CANDMAX) break;
        hi = t; lo = t;
        __syncthreads();
    }

    // ---- write pass (single memory write of the row) ----
    int localHi = 0, localCd = 0;
#pragma unroll
    for (int j = 0; j < 12; j++) {
        int q = j * 256 + tid;
        float4 o;
        float* fe = &f[j].x;
        float* oe = &o.x;
#pragma unroll
        for (int e = 0; e < 4; e++) {
            float v = fe[e];
            int idx = q * 4 + e;
            if (v > hi) {
                int slot = (int)hiBase + localHi;
                g_cvals[r * KTOP + slot] = v;
                g_cidx [r * KTOP + slot] = idx;
                localHi++;
                oe[e] = v;
            } else if (v >= lo) {
                int cpos = (int)cdBase + localCd;
                if (cpos < CANDMAX) g_cand[r * CANDMAX + cpos] = idx;
                localCd++;
                oe[e] = v;          // refine resolves
            } else {
                oe[e] = 0.f;
            }
        }
        ((float4*)src)[q] = o;
    }

    if (tid == 0) {
        int Cc = (int)C;
        if (Cc > CANDMAX) Cc = CANDMAX;
        g_G[r]    = (int)G;
        g_C[r]    = Cc;
        g_need[r] = KTOP - (int)G;
    }
}

// ---------------------------------------------------------------------------
// Kernel 2b: Eigen-exact candidate rescoring, k-panels {320,320,128}.
// (correctness anchor — arithmetic untouched)
// ---------------------------------------------------------------------------
__global__ __launch_bounds__(128)
void refine_kernel(const float* __restrict__ x,
                   const float* __restrict__ be,
                   const float* __restrict__ bd,
                   float* __restrict__ sparse)
{
    __shared__ float cval[CANDMAX];
    __shared__ int   cidx[CANDMAX];
    __shared__ float xs[DIN];

    const int r    = blockIdx.x;
    const int tid  = threadIdx.x;

    const int G    = g_G[r];
    const int C    = g_C[r];
    const int need = g_need[r];

    for (int k = tid; k < DIN; k += 128)
        xs[k] = x[(size_t)r * DIN + k] - bd[k];
    if (tid < C) cidx[tid] = g_cand[r * CANDMAX + tid];
    __syncthreads();

    if (tid < C) {
        const int col = cidx[tid];
        const float* w = g_WeT + (size_t)col * DIN;
        const int kcs[4] = {0, 320, 640, 768};
        float master = 0.f;
#pragma unroll 1
        for (int c = 0; c < 3; c++) {
            float chunk = 0.f;
#pragma unroll 4
            for (int k = kcs[c]; k < kcs[c + 1]; k++)
                chunk = fmaf(xs[k], w[k], chunk);
            master = master + chunk;
        }
        master = master + be[col];
        cval[tid] = fmaxf(master, 0.f);
    }
    __syncthreads();

    if (tid < C) {
        float v = cval[tid];
        int   i = cidx[tid];
        unsigned u = __float_as_uint(v);
        int rank = 0;
        for (int k = 0; k < C; k++) {
            unsigned uk = __float_as_uint(cval[k]);
            rank += (uk > u) || (uk == u && cidx[k] < i);
        }
        float* src = sparse + (size_t)r * DSAE;
        if (rank < need) {
            src[i] = v;
            int slot = G + rank;
            g_cvals[r * KTOP + slot] = v;
            g_cidx [r * KTOP + slot] = i;
        } else {
            src[i] = 0.f;
        }
    }
}

// ---------------------------------------------------------------------------
// Kernel 3: sparse decode (unchanged)
// ---------------------------------------------------------------------------
__global__ __launch_bounds__(256)
void decode_kernel(const float* __restrict__ Wd,
                   const float* __restrict__ bd,
                   float* __restrict__ recon)
{
    __shared__ float sv[KTOP];
    __shared__ int   si[KTOP];
    const int r   = blockIdx.x;
    const int tid = threadIdx.x;
    if (tid < KTOP) {
        sv[tid] = g_cvals[r * KTOP + tid];
        si[tid] = g_cidx [r * KTOP + tid];
    }
    __syncthreads();

    float a0 = bd[tid];
    float a1 = bd[tid + 256];
    float a2 = bd[tid + 512];
#pragma unroll 4
    for (int j = 0; j < KTOP; j++) {
        const float* w = Wd + (size_t)si[j] * DIN;
        float v = sv[j];
        a0 = fmaf(v, w[tid],       a0);
        a1 = fmaf(v, w[tid + 256], a1);
        a2 = fmaf(v, w[tid + 512], a2);
    }
    float* out = recon + (size_t)r * DIN;
    out[tid]       = a0;
    out[tid + 256] = a1;
    out[tid + 512] = a2;
}

// ---------------------------------------------------------------------------
extern "C" void kernel_launch(void* const* d_in, const int* in_sizes, int n_in,
                              void* d_out, int out_size)
{
    const float* x  = (const float*)d_in[0];
    const float* We = (const float*)d_in[1];
    const float* be = (const float*)d_in[2];
    const float* Wd = (const float*)d_in[3];
    const float* bd = (const float*)d_in[4];

    float* out    = (float*)d_out;
    float* recon  = out;
    float* sparse = out + (size_t)BATCH * DIN;

    cudaFuncSetAttribute(enc_gemm_mma,
                         cudaFuncAttributeMaxDynamicSharedMemorySize, GEMM_SMEM);

    convA<<<(BATCH * DIN + 255) / 256, 256>>>(x, bd);
    convB<<<dim3(DSAE / 32, DIN / 32), 256>>>(We);

    dim3 gemm_grid(DSAE / 128, BATCH / 128);   // (96, 64)
    enc_gemm_mma<<<gemm_grid, 256, GEMM_SMEM>>>(be, sparse);

    topk_kernel<<<BATCH, 256>>>(sparse);
    refine_kernel<<<BATCH, 128>>>(x, be, bd, sparse);
    decode_kernel<<<BATCH, 256>>>(Wd, bd, recon);
}

// round 14
// speedup vs baseline: 4.9890x; 1.6360x over previous
#include <cuda_runtime.h>
#include <cuda_fp16.h>
#include <cstdint>

#define BATCH 8192
#define DIN   768
#define DSAE  12288
#define KTOP  64
#define CANDMAX 128

// ---------------- scratch (__device__ globals = sanctioned scratch) --------
__device__ float g_cvals[BATCH * KTOP];
__device__ int   g_cidx [BATCH * KTOP];
__device__ int   g_G    [BATCH];
__device__ int   g_C    [BATCH];
__device__ int   g_need [BATCH];
__device__ int   g_cand [BATCH * CANDMAX];

// fp16 operands, K-major
__device__ __half g_A[BATCH * DIN];            // x - b_dec
__device__ __half g_B[DSAE * DIN];             // W_enc^T  [n][k]
// fp32 transposed encoder weights for refine
__device__ float g_WeT[(size_t)DSAE * DIN];

__device__ __forceinline__ uint32_t smem_u32(const void* p) {
    uint32_t a;
    asm("{ .reg .u64 t; cvta.to.shared.u64 t, %1; cvt.u32.u64 %0, t; }"
        : "=r"(a) : "l"(p));
    return a;
}
__device__ __forceinline__ void ldsm4(uint32_t* r, uint32_t addr) {
    asm volatile("ldmatrix.sync.aligned.m8n8.x4.shared.b16 {%0,%1,%2,%3}, [%4];"
                 : "=r"(r[0]), "=r"(r[1]), "=r"(r[2]), "=r"(r[3]) : "r"(addr));
}
__device__ __forceinline__ void mma16816h(float* c, const uint32_t* a, const uint32_t* b) {
    asm volatile(
        "mma.sync.aligned.m16n8k16.row.col.f32.f16.f16.f32 "
        "{%0,%1,%2,%3}, {%4,%5,%6,%7}, {%8,%9}, {%0,%1,%2,%3};"
        : "+f"(c[0]), "+f"(c[1]), "+f"(c[2]), "+f"(c[3])
        : "r"(a[0]), "r"(a[1]), "r"(a[2]), "r"(a[3]), "r"(b[0]), "r"(b[1]));
}
__device__ __forceinline__ void cp16(uint32_t saddr, const void* g) {
    asm volatile("cp.async.cg.shared.global [%0], [%1], 16;" :: "r"(saddr), "l"(g));
}

// ---------------------------------------------------------------------------
__global__ __launch_bounds__(256)
void convA(const float* __restrict__ x, const float* __restrict__ bd)
{
    int idx = blockIdx.x * 256 + threadIdx.x;
    if (idx >= BATCH * DIN) return;
    int k = idx % DIN;
    g_A[idx] = __float2half(x[idx] - bd[k]);
}

__global__ __launch_bounds__(256)
void convB(const float* __restrict__ We)
{
    __shared__ float tile[32][33];
    int tx = threadIdx.x & 31, ty = threadIdx.x >> 5;
    int nBase = blockIdx.x * 32;
    int kBase = blockIdx.y * 32;
#pragma unroll
    for (int r = 0; r < 4; r++)
        tile[ty + r * 8][tx] = We[(size_t)(kBase + ty + r * 8) * DSAE + nBase + tx];
    __syncthreads();
#pragma unroll
    for (int r = 0; r < 4; r++) {
        int n = nBase + ty + r * 8;
        int k = kBase + tx;
        float v = tile[tx][ty + r * 8];
        g_B  [(size_t)n * DIN + k] = __float2half(v);
        g_WeT[(size_t)n * DIN + k] = v;
    }
}

// ---------------------------------------------------------------------------
// Kernel 1: encoder GEMM, fp16 mma.sync, BK=64, 3-stage cp.async pipeline.
// CTA 128x128, 8 warps (2m x 4n), warp tile 64x32. 12 chunks, 24 barriers.
// ---------------------------------------------------------------------------
#define PADH 72                     // half row stride (144B = 128B data + 16B pad)
#define MATB (128 * PADH * 2)       // 18432 B per matrix per stage
#define STAGEB (2 * MATB)           // 36864 B per stage
#define NSTAGE 3
#define GEMM_SMEM (NSTAGE * STAGEB) // 110592 B

__global__ __launch_bounds__(256, 2)
void enc_gemm_mma(const float* __restrict__ be, float* __restrict__ pre)
{
    extern __shared__ char dsm[];
    const uint32_t sb = smem_u32(dsm);

    const int tid  = threadIdx.x;
    const int lane = tid & 31;
    const int wid  = tid >> 5;
    const int warpM = (wid >> 2) * 64;
    const int warpN = (wid & 3) * 32;
    const int mBase = blockIdx.y * 128;
    const int nBase = blockIdx.x * 128;

    float acc[4][4][4];
#pragma unroll
    for (int i = 0; i < 4; i++)
#pragma unroll
        for (int j = 0; j < 4; j++)
#pragma unroll
            for (int v = 0; v < 4; v++) acc[i][j][v] = 0.f;

    // per chunk per matrix: 128 rows x 128B = 1024 x 16B ops; 4 per thread
#define ISSUE_CHUNK(c, stage)                                                   \
    {                                                                           \
        int kof = (c) * 64;                                                     \
        uint32_t st = sb + (stage) * STAGEB;                                    \
        _Pragma("unroll")                                                       \
        for (int p = 0; p < 4; p++) {                                           \
            int id  = tid + p * 256;                                            \
            int row = id >> 3, seg = id & 7;                                    \
            uint32_t so = (uint32_t)(row * PADH + seg * 8) * 2;                 \
            size_t ga = (size_t)(mBase + row) * DIN + kof + seg * 8;            \
            size_t gb = (size_t)(nBase + row) * DIN + kof + seg * 8;            \
            cp16(st + so, g_A + ga);                                            \
            cp16(st + MATB + so, g_B + gb);                                     \
        }                                                                       \
    }

    const int aRow = lane & 15;
    const int aCol = (lane >> 4) * 8;
    const int bg   = lane >> 3;
    const int bRowOff = ((bg >> 1) * 8) + (lane & 7);
    const int bColOff = (bg & 1) * 8;

    ISSUE_CHUNK(0, 0);
    asm volatile("cp.async.commit_group;" ::: "memory");
    ISSUE_CHUNK(1, 1);
    asm volatile("cp.async.commit_group;" ::: "memory");

    for (int c = 0; c < DIN / 64; c++) {          // 12 chunks
        asm volatile("cp.async.wait_group 1;" ::: "memory");
        __syncthreads();

        if (c + 2 < DIN / 64) {
            ISSUE_CHUNK(c + 2, (c + 2) % NSTAGE);
            asm volatile("cp.async.commit_group;" ::: "memory");
        }

        uint32_t st = sb + (c % NSTAGE) * STAGEB;
        uint32_t uA = st, uB = st + MATB;

#pragma unroll
        for (int ks = 0; ks < 4; ks++) {
            uint32_t a[4][4];
#pragma unroll
            for (int mt = 0; mt < 4; mt++) {
                uint32_t off = (uint32_t)((warpM + mt * 16 + aRow) * PADH +
                                          ks * 16 + aCol) * 2;
                ldsm4(a[mt], uA + off);
            }
            uint32_t b[4][2];
#pragma unroll
            for (int i = 0; i < 2; i++) {
                uint32_t off = (uint32_t)((warpN + i * 16 + bRowOff) * PADH +
                                          bColOff + ks * 16) * 2;
                uint32_t t[4];
                ldsm4(t, uB + off);
                b[2 * i][0] = t[0]; b[2 * i][1] = t[1];
                b[2 * i + 1][0] = t[2]; b[2 * i + 1][1] = t[3];
            }
#pragma unroll
            for (int mt = 0; mt < 4; mt++)
#pragma unroll
                for (int nt = 0; nt < 4; nt++)
                    mma16816h(acc[mt][nt], a[mt], b[nt]);
        }
        __syncthreads();
    }

    // epilogue: +b_enc, relu, store
#pragma unroll
    for (int mt = 0; mt < 4; mt++) {
#pragma unroll
        for (int nt = 0; nt < 4; nt++) {
            int m0 = mBase + warpM + mt * 16 + (lane >> 2);
            int n0 = nBase + warpN + nt * 8 + (lane & 3) * 2;
            float2 bev = *(const float2*)(be + n0);
            float2 o;
            o.x = fmaxf(acc[mt][nt][0] + bev.x, 0.f);
            o.y = fmaxf(acc[mt][nt][1] + bev.y, 0.f);
            *(float2*)(pre + (size_t)m0 * DSAE + n0) = o;
            o.x = fmaxf(acc[mt][nt][2] + bev.x, 0.f);
            o.y = fmaxf(acc[mt][nt][3] + bev.y, 0.f);
            *(float2*)(pre + (size_t)(m0 + 8) * DSAE + n0) = o;
        }
    }
}

// ---------------------------------------------------------------------------
// block exclusive scan over 256 threads (shfl + 8 warp partials)
// ---------------------------------------------------------------------------
__device__ __forceinline__ unsigned block_scan_excl(unsigned v, unsigned* wsum,
                                                    unsigned& total)
{
    const int lane = threadIdx.x & 31, w = threadIdx.x >> 5;
    unsigned incl = v;
#pragma unroll
    for (int o = 1; o < 32; o <<= 1) {
        unsigned n = __shfl_up_sync(0xffffffffu, incl, o);
        if (lane >= o) incl += n;
    }
    if (lane == 31) wsum[w] = incl;
    __syncthreads();
    if (w == 0) {
        unsigned s = (lane < 8) ? wsum[lane] : 0u;
#pragma unroll
        for (int o = 1; o < 8; o <<= 1) {
            unsigned n = __shfl_up_sync(0xffffffffu, s, o);
            if (lane >= o) s += n;
        }
        if (lane < 8) wsum[lane] = s;
    }
    __syncthreads();
    unsigned base = w ? wsum[w - 1] : 0u;
    total = wsum[7];
    return base + incl - v;
}

// ---------------------------------------------------------------------------
// Kernel 2: streaming per-row top-64 (R11 shape: low regs, high occupancy).
// Margin 4e-3*t absorbs fp16 GEMM noise; band resolved exactly in refine.
// ---------------------------------------------------------------------------
__global__ __launch_bounds__(256)
void topk_kernel(float* __restrict__ sparse)
{
    __shared__ unsigned hist[256];
    __shared__ unsigned wsum[8];
    __shared__ unsigned sh_bin, sh_need;

    const int r   = blockIdx.x;
    const int tid = threadIdx.x;
    float* src = sparse + (size_t)r * DSAE;
    const float4* s4 = (const float4*)src;

    unsigned sel = 0, selmask = 0;
    int kneed = KTOP;
    for (int shift = 24; shift >= 0; shift -= 8) {
        hist[tid] = 0;
        __syncthreads();
#pragma unroll 2
        for (int j = 0; j < 12; j++) {
            float4 f = s4[j * 256 + tid];
            unsigned u;
            u = __float_as_uint(f.x); if ((u & selmask) == sel) atomicAdd(&hist[(u >> shift) & 255u], 1u);
            u = __float_as_uint(f.y); if ((u & selmask) == sel) atomicAdd(&hist[(u >> shift) & 255u], 1u);
            u = __float_as_uint(f.z); if ((u & selmask) == sel) atomicAdd(&hist[(u >> shift) & 255u], 1u);
            u = __float_as_uint(f.w); if ((u & selmask) == sel) atomicAdd(&hist[(u >> shift) & 255u], 1u);
        }
        __syncthreads();
        unsigned v = hist[255 - tid];
        unsigned total, excl = block_scan_excl(v, wsum, total);
        if ((int)excl < kneed && (int)(excl + v) >= kneed) {
            sh_bin  = (unsigned)(255 - tid);
            sh_need = (unsigned)(kneed - (int)excl);
        }
        __syncthreads();
        sel     |= sh_bin << shift;
        selmask |= 255u << shift;
        kneed    = (int)sh_need;
        __syncthreads();
    }

    const float t = __uint_as_float(sel);

    float m = t * 4e-3f;
    float hi = t + m, lo = t - m;
    unsigned hiBase = 0, cdBase = 0, G = 0, C = 0;

    for (int attempt = 0; attempt < 2; attempt++) {
        unsigned cHi = 0, cCd = 0;
#pragma unroll 2
        for (int j = 0; j < 12; j++) {
            float4 f = s4[j * 256 + tid];
            cHi += (f.x > hi) + (f.y > hi) + (f.z > hi) + (f.w > hi);
            cCd += ((f.x >= lo) & (f.x <= hi)) + ((f.y >= lo) & (f.y <= hi))
                 + ((f.z >= lo) & (f.z <= hi)) + ((f.w >= lo) & (f.w <= hi));
        }
        unsigned mine = (cHi << 16) | cCd;
        unsigned total, excl = block_scan_excl(mine, wsum, total);
        hiBase = excl >> 16;  cdBase = excl & 0xffffu;
        G = total >> 16;      C = total & 0xffffu;
        if (C <= CANDMAX) break;
        hi = t; lo = t;
        __syncthreads();
    }

    int localHi = 0, localCd = 0;
#pragma unroll 2
    for (int j = 0; j < 12; j++) {
        int q = j * 256 + tid;
        float4 f = s4[q];
        float4 o;
        float* fe = &f.x;
        float* oe = &o.x;
#pragma unroll
        for (int e = 0; e < 4; e++) {
            float v = fe[e];
            int idx = q * 4 + e;
            if (v > hi) {
                int slot = (int)hiBase + localHi;
                g_cvals[r * KTOP + slot] = v;
                g_cidx [r * KTOP + slot] = idx;
                localHi++;
                oe[e] = v;
            } else if (v >= lo) {
                int cpos = (int)cdBase + localCd;
                if (cpos < CANDMAX) g_cand[r * CANDMAX + cpos] = idx;
                localCd++;
                oe[e] = v;          // refine resolves
            } else {
                oe[e] = 0.f;
            }
        }
        ((float4*)src)[q] = o;
    }

    if (tid == 0) {
        int Cc = (int)C;
        if (Cc > CANDMAX) Cc = CANDMAX;
        g_G[r]    = (int)G;
        g_C[r]    = Cc;
        g_need[r] = KTOP - (int)G;
    }
}

// ---------------------------------------------------------------------------
// Kernel 2b: Eigen-exact candidate rescoring, k-panels {320,320,128}.
// (correctness anchor — arithmetic untouched)
// ---------------------------------------------------------------------------
__global__ __launch_bounds__(128)
void refine_kernel(const float* __restrict__ x,
                   const float* __restrict__ be,
                   const float* __restrict__ bd,
                   float* __restrict__ sparse)
{
    __shared__ float cval[CANDMAX];
    __shared__ int   cidx[CANDMAX];
    __shared__ float xs[DIN];

    const int r    = blockIdx.x;
    const int tid  = threadIdx.x;

    const int G    = g_G[r];
    const int C    = g_C[r];
    const int need = g_need[r];

    for (int k = tid; k < DIN; k += 128)
        xs[k] = x[(size_t)r * DIN + k] - bd[k];
    if (tid < C) cidx[tid] = g_cand[r * CANDMAX + tid];
    __syncthreads();

    if (tid < C) {
        const int col = cidx[tid];
        const float* w = g_WeT + (size_t)col * DIN;
        const int kcs[4] = {0, 320, 640, 768};
        float master = 0.f;
#pragma unroll 1
        for (int c = 0; c < 3; c++) {
            float chunk = 0.f;
#pragma unroll 4
            for (int k = kcs[c]; k < kcs[c + 1]; k++)
                chunk = fmaf(xs[k], w[k], chunk);
            master = master + chunk;
        }
        master = master + be[col];
        cval[tid] = fmaxf(master, 0.f);
    }
    __syncthreads();

    if (tid < C) {
        float v = cval[tid];
        int   i = cidx[tid];
        unsigned u = __float_as_uint(v);
        int rank = 0;
        for (int k = 0; k < C; k++) {
            unsigned uk = __float_as_uint(cval[k]);
            rank += (uk > u) || (uk == u && cidx[k] < i);
        }
        float* src = sparse + (size_t)r * DSAE;
        if (rank < need) {
            src[i] = v;
            int slot = G + rank;
            g_cvals[r * KTOP + slot] = v;
            g_cidx [r * KTOP + slot] = i;
        } else {
            src[i] = 0.f;
        }
    }
}

// ---------------------------------------------------------------------------
// Kernel 3: sparse decode (unchanged)
// ---------------------------------------------------------------------------
__global__ __launch_bounds__(256)
void decode_kernel(const float* __restrict__ Wd,
                   const float* __restrict__ bd,
                   float* __restrict__ recon)
{
    __shared__ float sv[KTOP];
    __shared__ int   si[KTOP];
    const int r   = blockIdx.x;
    const int tid = threadIdx.x;
    if (tid < KTOP) {
        sv[tid] = g_cvals[r * KTOP + tid];
        si[tid] = g_cidx [r * KTOP + tid];
    }
    __syncthreads();

    float a0 = bd[tid];
    float a1 = bd[tid + 256];
    float a2 = bd[tid + 512];
#pragma unroll 4
    for (int j = 0; j < KTOP; j++) {
        const float* w = Wd + (size_t)si[j] * DIN;
        float v = sv[j];
        a0 = fmaf(v, w[tid],       a0);
        a1 = fmaf(v, w[tid + 256], a1);
        a2 = fmaf(v, w[tid + 512], a2);
    }
    float* out = recon + (size_t)r * DIN;
    out[tid]       = a0;
    out[tid + 256] = a1;
    out[tid + 512] = a2;
}

// ---------------------------------------------------------------------------
extern "C" void kernel_launch(void* const* d_in, const int* in_sizes, int n_in,
                              void* d_out, int out_size)
{
    const float* x  = (const float*)d_in[0];
    const float* We = (const float*)d_in[1];
    const float* be = (const float*)d_in[2];
    const float* Wd = (const float*)d_in[3];
    const float* bd = (const float*)d_in[4];

    float* out    = (float*)d_out;
    float* recon  = out;
    float* sparse = out + (size_t)BATCH * DIN;

    cudaFuncSetAttribute(enc_gemm_mma,
                         cudaFuncAttributeMaxDynamicSharedMemorySize, GEMM_SMEM);

    convA<<<(BATCH * DIN + 255) / 256, 256>>>(x, bd);
    convB<<<dim3(DSAE / 32, DIN / 32), 256>>>(We);

    dim3 gemm_grid(DSAE / 128, BATCH / 128);   // (96, 64)
    enc_gemm_mma<<<gemm_grid, 256, GEMM_SMEM>>>(be, sparse);

    topk_kernel<<<BATCH, 256>>>(sparse);
    refine_kernel<<<BATCH, 128>>>(x, be, bd, sparse);
    decode_kernel<<<BATCH, 256>>>(Wd, bd, recon);
}